// round 1
// baseline (speedup 1.0000x reference)
#include <cuda_runtime.h>
#include <math.h>

// Problem constants
#define Bb 4
#define Tt 2048
#define Cc 1024
#define Hh 16
#define HD 64
#define Mrows (Bb*Tt)   // 8192

// Scratch (allocation-free: __device__ globals)
__device__ float g_Q[(size_t)Bb*Hh*Tt*HD];
__device__ float g_K[(size_t)Bb*Hh*Tt*HD];
__device__ float g_V[(size_t)Bb*Hh*Tt*HD];
__device__ float g_Y[(size_t)Bb*Tt*Cc];

// ---------------------------------------------------------------------------
// NT SGEMM: out[m][n] = sum_k A[m][k] * W[n][k] (+ bias[n])
// M=8192, N=1024, K=1024. Block 128x128, BK=8, thread tile 8x8, 256 threads.
// head_layout=1: scatter n -> (h,d), m -> (b,t) into (B,H,T,HD) tensor.
// ---------------------------------------------------------------------------
__global__ __launch_bounds__(256) void gemm_nt(
    const float* __restrict__ A, const float* __restrict__ W,
    const float* __restrict__ bias, float* __restrict__ out,
    int head_layout)
{
    const int K = Cc, N = Cc;
    __shared__ float As[8][128];
    __shared__ float Ws[8][128];
    int tid = threadIdx.x;
    int bm = blockIdx.y * 128, bn = blockIdx.x * 128;
    int tx = tid & 15, ty = tid >> 4;

    float acc[8][8];
#pragma unroll
    for (int i = 0; i < 8; i++)
#pragma unroll
        for (int j = 0; j < 8; j++) acc[i][j] = 0.f;

    int lr = tid >> 1;          // 0..127: row within tile
    int lc = (tid & 1) << 2;    // 0 or 4: k offset
    const float* Ap = A + (size_t)(bm + lr) * K + lc;
    const float* Wp = W + (size_t)(bn + lr) * K + lc;

    for (int k0 = 0; k0 < K; k0 += 8) {
        float4 a = *(const float4*)(Ap + k0);
        float4 w = *(const float4*)(Wp + k0);
        As[lc + 0][lr] = a.x; As[lc + 1][lr] = a.y;
        As[lc + 2][lr] = a.z; As[lc + 3][lr] = a.w;
        Ws[lc + 0][lr] = w.x; Ws[lc + 1][lr] = w.y;
        Ws[lc + 2][lr] = w.z; Ws[lc + 3][lr] = w.w;
        __syncthreads();
#pragma unroll
        for (int k = 0; k < 8; k++) {
            float4 a0 = *(const float4*)&As[k][ty * 8];
            float4 a1 = *(const float4*)&As[k][ty * 8 + 4];
            float4 w0 = *(const float4*)&Ws[k][tx * 8];
            float4 w1 = *(const float4*)&Ws[k][tx * 8 + 4];
            float ar[8] = {a0.x, a0.y, a0.z, a0.w, a1.x, a1.y, a1.z, a1.w};
            float wr[8] = {w0.x, w0.y, w0.z, w0.w, w1.x, w1.y, w1.z, w1.w};
#pragma unroll
            for (int i = 0; i < 8; i++)
#pragma unroll
                for (int j = 0; j < 8; j++)
                    acc[i][j] += ar[i] * wr[j];
        }
        __syncthreads();
    }

    if (head_layout) {
        // n stays inside one 64-wide head slice per 8-run (tx*8 aligned)
        int n0 = bn + tx * 8;
        int h = n0 >> 6, d0 = n0 & 63;
#pragma unroll
        for (int i = 0; i < 8; i++) {
            int m = bm + ty * 8 + i;
            int b = m >> 11, t = m & (Tt - 1);
            float* dst = out + ((size_t)(b * Hh + h) * Tt + t) * HD + d0;
            *(float4*)dst       = make_float4(acc[i][0], acc[i][1], acc[i][2], acc[i][3]);
            *(float4*)(dst + 4) = make_float4(acc[i][4], acc[i][5], acc[i][6], acc[i][7]);
        }
    } else {
        int n0 = bn + tx * 8;
        float bv[8];
#pragma unroll
        for (int j = 0; j < 8; j++) bv[j] = bias ? bias[n0 + j] : 0.f;
#pragma unroll
        for (int i = 0; i < 8; i++) {
            int m = bm + ty * 8 + i;
            float* dst = out + (size_t)m * N + n0;
            *(float4*)dst       = make_float4(acc[i][0] + bv[0], acc[i][1] + bv[1],
                                              acc[i][2] + bv[2], acc[i][3] + bv[3]);
            *(float4*)(dst + 4) = make_float4(acc[i][4] + bv[4], acc[i][5] + bv[5],
                                              acc[i][6] + bv[6], acc[i][7] + bv[7]);
        }
    }
}

// ---------------------------------------------------------------------------
// Causal flash attention, fp32. Q/K/V: (B*H, T, 64). Output Y: (B, T, C).
// CTA = 64 query rows. 256 threads as 16x16, thread tile 4x4.
// Smem tiles 64x64, XOR-swizzled on 4-float blocks for transposed tiles.
// ---------------------------------------------------------------------------
__device__ __forceinline__ void tstore(float* base, int d, int r, float v) {
    base[d * 64 + ((((r >> 2) ^ (d >> 2)) & 15) << 2) + (r & 3)] = v;
}

__global__ __launch_bounds__(256) void flash_attn(
    const float* __restrict__ Qg, const float* __restrict__ Kg,
    const float* __restrict__ Vg, float* __restrict__ Yg)
{
    extern __shared__ float smp[];
    float* Qs = smp;            // transposed swizzled [d][r]
    float* Ks = smp + 4096;     // transposed swizzled [d][c]
    float* Vs = smp + 8192;     // natural [c][d]
    float* Ps = smp + 12288;    // transposed swizzled [c][r]

    int tid = threadIdx.x;
    int tx = tid & 15, ty = tid >> 4;
    int qb = blockIdx.x;        // query block 0..31
    int bh = blockIdx.y;        // 0..63

    const float* Qbase = Qg + ((size_t)bh * Tt + qb * 64) * HD;
    const float* Kbase = Kg + (size_t)bh * Tt * HD;
    const float* Vbase = Vg + (size_t)bh * Tt * HD;

    // Load Q tile transposed (once)
    for (int i = tid; i < 1024; i += 256) {
        int r = i >> 4, d4 = (i & 15) << 2;
        float4 v = *(const float4*)(Qbase + r * HD + d4);
        tstore(Qs, d4 + 0, r, v.x); tstore(Qs, d4 + 1, r, v.y);
        tstore(Qs, d4 + 2, r, v.z); tstore(Qs, d4 + 3, r, v.w);
    }
    __syncthreads();

    float o[4][4];
    float mrow[4], lrow[4];
#pragma unroll
    for (int i = 0; i < 4; i++) {
        mrow[i] = -INFINITY; lrow[i] = 0.f;
#pragma unroll
        for (int j = 0; j < 4; j++) o[i][j] = 0.f;
    }

    const float scale = 0.125f;  // 1/sqrt(64)
    int qr0 = qb * 64 + ty * 4;
    int kc0t = tx * 4;

    for (int kb = 0; kb <= qb; kb++) {
        // Load K (transposed) and V (natural)
        for (int i = tid; i < 1024; i += 256) {
            int c = i >> 4, d4 = (i & 15) << 2;
            float4 kv = *(const float4*)(Kbase + (size_t)(kb * 64 + c) * HD + d4);
            tstore(Ks, d4 + 0, c, kv.x); tstore(Ks, d4 + 1, c, kv.y);
            tstore(Ks, d4 + 2, c, kv.z); tstore(Ks, d4 + 3, c, kv.w);
            float4 vv = *(const float4*)(Vbase + (size_t)(kb * 64 + c) * HD + d4);
            *(float4*)&Vs[c * 64 + d4] = vv;
        }
        __syncthreads();

        // S = Q @ K^T (64x64), thread tile 4x4
        float s[4][4];
#pragma unroll
        for (int i = 0; i < 4; i++)
#pragma unroll
            for (int j = 0; j < 4; j++) s[i][j] = 0.f;
#pragma unroll 4
        for (int d = 0; d < 64; d++) {
            float4 qv = *(const float4*)(Qs + d * 64 + (((ty ^ (d >> 2)) & 15) << 2));
            float4 kv = *(const float4*)(Ks + d * 64 + (((tx ^ (d >> 2)) & 15) << 2));
            float qa[4] = {qv.x, qv.y, qv.z, qv.w};
            float ka[4] = {kv.x, kv.y, kv.z, kv.w};
#pragma unroll
            for (int i = 0; i < 4; i++)
#pragma unroll
                for (int j = 0; j < 4; j++)
                    s[i][j] += qa[i] * ka[j];
        }

        // Scale + causal mask
        int kc0 = kb * 64 + kc0t;
#pragma unroll
        for (int i = 0; i < 4; i++)
#pragma unroll
            for (int j = 0; j < 4; j++) {
                float v = s[i][j] * scale;
                if (kc0 + j > qr0 + i) v = -INFINITY;
                s[i][j] = v;
            }

        // Online softmax (row groups = 16 tx lanes, shuffle within 16-lane half)
#pragma unroll
        for (int i = 0; i < 4; i++) {
            float v = fmaxf(fmaxf(s[i][0], s[i][1]), fmaxf(s[i][2], s[i][3]));
            v = fmaxf(v, __shfl_xor_sync(0xffffffffu, v, 8));
            v = fmaxf(v, __shfl_xor_sync(0xffffffffu, v, 4));
            v = fmaxf(v, __shfl_xor_sync(0xffffffffu, v, 2));
            v = fmaxf(v, __shfl_xor_sync(0xffffffffu, v, 1));
            float mnew = fmaxf(mrow[i], v);
            float alpha = __expf(mrow[i] - mnew);
            mrow[i] = mnew;
            float rs = 0.f;
#pragma unroll
            for (int j = 0; j < 4; j++) {
                s[i][j] = __expf(s[i][j] - mnew);
                rs += s[i][j];
            }
            rs += __shfl_xor_sync(0xffffffffu, rs, 8);
            rs += __shfl_xor_sync(0xffffffffu, rs, 4);
            rs += __shfl_xor_sync(0xffffffffu, rs, 2);
            rs += __shfl_xor_sync(0xffffffffu, rs, 1);
            lrow[i] = lrow[i] * alpha + rs;
#pragma unroll
            for (int j = 0; j < 4; j++) o[i][j] *= alpha;
        }

        // Store P transposed: element (c = tx*4+j, r = ty*4+i)
#pragma unroll
        for (int i = 0; i < 4; i++)
#pragma unroll
            for (int j = 0; j < 4; j++)
                tstore(Ps, tx * 4 + j, ty * 4 + i, s[i][j]);
        __syncthreads();

        // O += P @ V
#pragma unroll 4
        for (int c = 0; c < 64; c++) {
            float4 pv = *(const float4*)(Ps + c * 64 + (((ty ^ (c >> 2)) & 15) << 2));
            float4 vv = *(const float4*)(Vs + c * 64 + tx * 4);
            float pa[4] = {pv.x, pv.y, pv.z, pv.w};
            float va[4] = {vv.x, vv.y, vv.z, vv.w};
#pragma unroll
            for (int i = 0; i < 4; i++)
#pragma unroll
                for (int j = 0; j < 4; j++)
                    o[i][j] += pa[i] * va[j];
        }
        __syncthreads();   // before next iteration's K/V/P overwrite
    }

    // Normalize and write Y in (B,T,C)
    int b = bh >> 4, h = bh & 15;
#pragma unroll
    for (int i = 0; i < 4; i++) {
        float inv = 1.0f / lrow[i];
        int t = qb * 64 + ty * 4 + i;
        float* dst = Yg + ((size_t)(b * Tt + t)) * Cc + h * 64 + tx * 4;
        *(float4*)dst = make_float4(o[i][0] * inv, o[i][1] * inv,
                                    o[i][2] * inv, o[i][3] * inv);
    }
}

// ---------------------------------------------------------------------------
extern "C" void kernel_launch(void* const* d_in, const int* in_sizes, int n_in,
                              void* d_out, int out_size)
{
    const float* xq = (const float*)d_in[0];
    const float* xk = (const float*)d_in[1];
    const float* xv = (const float*)d_in[2];
    const float* Wq = (const float*)d_in[3];
    const float* Wk = (const float*)d_in[4];
    const float* Wv = (const float*)d_in[5];
    const float* Wo = (const float*)d_in[6];
    const float* bo = (const float*)d_in[7];
    float* out = (float*)d_out;

    float *Qp, *Kp, *Vp, *Yp;
    cudaGetSymbolAddress((void**)&Qp, g_Q);
    cudaGetSymbolAddress((void**)&Kp, g_K);
    cudaGetSymbolAddress((void**)&Vp, g_V);
    cudaGetSymbolAddress((void**)&Yp, g_Y);

    dim3 gemm_grid(Cc / 128, Mrows / 128);   // (8, 64)

    gemm_nt<<<gemm_grid, 256>>>(xq, Wq, nullptr, Qp, 1);
    gemm_nt<<<gemm_grid, 256>>>(xk, Wk, nullptr, Kp, 1);
    gemm_nt<<<gemm_grid, 256>>>(xv, Wv, nullptr, Vp, 1);

    static int smem_set = 0;
    (void)smem_set;
    cudaFuncSetAttribute(flash_attn, cudaFuncAttributeMaxDynamicSharedMemorySize, 65536);
    flash_attn<<<dim3(Tt / 64, Bb * Hh), 256, 65536>>>(Qp, Kp, Vp, Yp);

    gemm_nt<<<gemm_grid, 256>>>(Yp, Wo, bo, out, 0);
}

// round 3
// speedup vs baseline: 1.6748x; 1.6748x over previous
#include <cuda_runtime.h>
#include <math.h>
#include <stdint.h>

// Problem constants
#define Bb 4
#define Tt 2048
#define Cc 1024
#define Hh 16
#define HD 64
#define Mrows (Bb*Tt)   // 8192
#define GK 1024

// ---------------------------------------------------------------------------
// Helpers
// ---------------------------------------------------------------------------
__device__ __forceinline__ uint32_t smem_u32(const void* p) {
    uint32_t a;
    asm("{ .reg .u64 t; cvta.to.shared.u64 t, %1; cvt.u32.u64 %0, t; }"
        : "=r"(a) : "l"(p));
    return a;
}

__device__ __forceinline__ void cp_async16(uint32_t dst, const void* src) {
    asm volatile("cp.async.cg.shared.global [%0], [%1], 16;"
                 :: "r"(dst), "l"(src) : "memory");
}

__device__ __forceinline__ float round_tf32(float x) {
    uint32_t u;
    asm("cvt.rna.tf32.f32 %0, %1;" : "=r"(u) : "f"(x));
    return __uint_as_float(u);
}

// mma.sync m16n8k8 tf32 (base ISA, maps to HMMA on sm_103a)
__device__ __forceinline__ void mma16n8k8(
    float* c, const uint32_t* a, const uint32_t* b)
{
    asm volatile(
        "mma.sync.aligned.m16n8k8.row.col.f32.tf32.tf32.f32 "
        "{%0,%1,%2,%3}, {%4,%5,%6,%7}, {%8,%9}, {%0,%1,%2,%3};"
        : "+f"(c[0]), "+f"(c[1]), "+f"(c[2]), "+f"(c[3])
        : "r"(a[0]), "r"(a[1]), "r"(a[2]), "r"(a[3]),
          "r"(b[0]), "r"(b[1]));
}

// ---------------------------------------------------------------------------
// Scratch (allocation-free: __device__ globals)
// ---------------------------------------------------------------------------
__device__ float g_rxq[(size_t)Mrows*Cc];
__device__ float g_rxk[(size_t)Mrows*Cc];
__device__ float g_rxv[(size_t)Mrows*Cc];
__device__ float g_rWq[(size_t)Cc*Cc];
__device__ float g_rWk[(size_t)Cc*Cc];
__device__ float g_rWv[(size_t)Cc*Cc];
__device__ float g_rWo[(size_t)Cc*Cc];
__device__ float g_Q[(size_t)Bb*Hh*Tt*HD];
__device__ float g_K[(size_t)Bb*Hh*Tt*HD];
__device__ float g_V[(size_t)Bb*Hh*Tt*HD];
__device__ float g_Y[(size_t)Bb*Tt*Cc];

// ---------------------------------------------------------------------------
// RNA-round fp32 -> tf32-valued fp32
// ---------------------------------------------------------------------------
__global__ __launch_bounds__(256) void round_kernel(
    const float4* __restrict__ src, float4* __restrict__ dst, int n4)
{
    int i = blockIdx.x * blockDim.x + threadIdx.x;
    int stride = gridDim.x * blockDim.x;
    for (; i < n4; i += stride) {
        float4 v = src[i];
        v.x = round_tf32(v.x); v.y = round_tf32(v.y);
        v.z = round_tf32(v.z); v.w = round_tf32(v.w);
        dst[i] = v;
    }
}

// ---------------------------------------------------------------------------
// tf32 mma.sync NT GEMM: out[m][n] = sum_k A[m][k]*W[n][k] (+bias)
// BM=128, BN=128, BK=32. 8 warps (2m x 4n), warp tile 64x32 (4x4 m16n8k8).
// Smem [row][36] padded layout -> conflict-free fragment LDS.
// head_layout=1: scatter n->(h,d), m->(b,t) into (B,H,T,64).
// ---------------------------------------------------------------------------
#define PADK 36
#define STGF (128*PADK*2)      // floats per stage (A tile + B tile) = 9216
#define GEMM_SMEM (2*STGF*4)   // 73728 bytes
#define KTILES (GK/32)         // 32

__global__ __launch_bounds__(256, 1) void gemm_mma(
    const float* __restrict__ A, const float* __restrict__ W,
    const float* __restrict__ bias, float* __restrict__ out, int head_layout)
{
    extern __shared__ __align__(16) float dsm[];
    const int tid = threadIdx.x;
    const int wid = tid >> 5, lane = tid & 31;
    const int wm = wid & 1, wn = wid >> 1;      // 2 x 4 warp grid
    const int bm = blockIdx.y * 128, bn = blockIdx.x * 128;

    const uint32_t sbase = smem_u32(dsm);
    const int lg = lane >> 2;   // 0..7
    const int lk = lane & 3;    // 0..3

    float c[4][4][4];
#pragma unroll
    for (int i = 0; i < 4; i++)
#pragma unroll
        for (int j = 0; j < 4; j++)
#pragma unroll
            for (int r = 0; r < 4; r++) c[i][j][r] = 0.f;

    // async copy of one stage (A 128x32 + B 128x32)
    const int ch_m = tid >> 3;          // 0..31 (row block per 256-thread pass)
    const int ch_k = (tid & 7) << 2;    // 0,4,...,28

    {   // prologue stage 0
        uint32_t a_s = sbase, b_s = sbase + 128 * PADK * 4;
#pragma unroll
        for (int i = 0; i < 4; i++) {
            int m = ch_m + i * 32;
            uint32_t so = (uint32_t)(m * PADK + ch_k) * 4;
            cp_async16(a_s + so, A + (size_t)(bm + m) * GK + ch_k);
            cp_async16(b_s + so, W + (size_t)(bn + m) * GK + ch_k);
        }
        asm volatile("cp.async.commit_group;" ::: "memory");
    }

    for (int it = 0; it < KTILES; ++it) {
        if (it + 1 < KTILES) {
            int s = (it + 1) & 1;
            int kt = (it + 1) * 32;
            uint32_t a_s = sbase + s * STGF * 4, b_s = a_s + 128 * PADK * 4;
#pragma unroll
            for (int i = 0; i < 4; i++) {
                int m = ch_m + i * 32;
                uint32_t so = (uint32_t)(m * PADK + ch_k) * 4;
                cp_async16(a_s + so, A + (size_t)(bm + m) * GK + kt + ch_k);
                cp_async16(b_s + so, W + (size_t)(bn + m) * GK + kt + ch_k);
            }
            asm volatile("cp.async.commit_group;" ::: "memory");
            asm volatile("cp.async.wait_group 1;" ::: "memory");
        } else {
            asm volatile("cp.async.wait_group 0;" ::: "memory");
        }
        __syncthreads();

        const float* As = dsm + (it & 1) * STGF;
        const float* Bs = As + 128 * PADK;

#pragma unroll
        for (int kk = 0; kk < 32; kk += 8) {
            uint32_t af[4][4], bf[4][2];
#pragma unroll
            for (int mt = 0; mt < 4; mt++) {
                int r = wm * 64 + mt * 16 + lg;
                af[mt][0] = __float_as_uint(As[r * PADK + kk + lk]);
                af[mt][1] = __float_as_uint(As[(r + 8) * PADK + kk + lk]);
                af[mt][2] = __float_as_uint(As[r * PADK + kk + 4 + lk]);
                af[mt][3] = __float_as_uint(As[(r + 8) * PADK + kk + 4 + lk]);
            }
#pragma unroll
            for (int nt = 0; nt < 4; nt++) {
                int n = wn * 32 + nt * 8 + lg;
                bf[nt][0] = __float_as_uint(Bs[n * PADK + kk + lk]);
                bf[nt][1] = __float_as_uint(Bs[n * PADK + kk + 4 + lk]);
            }
#pragma unroll
            for (int mt = 0; mt < 4; mt++)
#pragma unroll
                for (int nt = 0; nt < 4; nt++)
                    mma16n8k8(c[mt][nt], af[mt], bf[nt]);
        }
        __syncthreads();
    }

    // Epilogue. c[mt][nt]: rows r0 = bm+wm*64+mt*16+lg (+8), cols
    // n = bn+wn*32+nt*8+lk*2 (+1).
#pragma unroll
    for (int mt = 0; mt < 4; mt++) {
        int r0 = bm + wm * 64 + mt * 16 + lg;
#pragma unroll
        for (int nt = 0; nt < 4; nt++) {
            int n = bn + wn * 32 + nt * 8 + lk * 2;
            if (head_layout) {
                int h = n >> 6, d = n & 63;
                int b0 = r0 >> 11, t0 = r0 & (Tt - 1);
                float* dst0 = out + ((size_t)(b0 * Hh + h) * Tt + t0) * HD + d;
                *(float2*)dst0 = make_float2(c[mt][nt][0], c[mt][nt][1]);
                int r1 = r0 + 8;
                int b1 = r1 >> 11, t1 = r1 & (Tt - 1);
                float* dst1 = out + ((size_t)(b1 * Hh + h) * Tt + t1) * HD + d;
                *(float2*)dst1 = make_float2(c[mt][nt][2], c[mt][nt][3]);
            } else {
                float2 bv = bias ? *(const float2*)(bias + n) : make_float2(0.f, 0.f);
                float* dst0 = out + (size_t)r0 * Cc + n;
                *(float2*)dst0 = make_float2(c[mt][nt][0] + bv.x, c[mt][nt][1] + bv.y);
                float* dst1 = out + (size_t)(r0 + 8) * Cc + n;
                *(float2*)dst1 = make_float2(c[mt][nt][2] + bv.x, c[mt][nt][3] + bv.y);
            }
        }
    }
}

// ---------------------------------------------------------------------------
// Causal flash attention, fp32 (known-correct from R1)
// ---------------------------------------------------------------------------
__device__ __forceinline__ void tstore(float* base, int d, int r, float v) {
    base[d * 64 + ((((r >> 2) ^ (d >> 2)) & 15) << 2) + (r & 3)] = v;
}

__global__ __launch_bounds__(256) void flash_attn(
    const float* __restrict__ Qg, const float* __restrict__ Kg,
    const float* __restrict__ Vg, float* __restrict__ Yg)
{
    extern __shared__ float smp[];
    float* Qs = smp;
    float* Ks = smp + 4096;
    float* Vs = smp + 8192;
    float* Ps = smp + 12288;

    int tid = threadIdx.x;
    int tx = tid & 15, ty = tid >> 4;
    int qb = blockIdx.x;
    int bh = blockIdx.y;

    const float* Qbase = Qg + ((size_t)bh * Tt + qb * 64) * HD;
    const float* Kbase = Kg + (size_t)bh * Tt * HD;
    const float* Vbase = Vg + (size_t)bh * Tt * HD;

    for (int i = tid; i < 1024; i += 256) {
        int r = i >> 4, d4 = (i & 15) << 2;
        float4 v = *(const float4*)(Qbase + r * HD + d4);
        tstore(Qs, d4 + 0, r, v.x); tstore(Qs, d4 + 1, r, v.y);
        tstore(Qs, d4 + 2, r, v.z); tstore(Qs, d4 + 3, r, v.w);
    }
    __syncthreads();

    float o[4][4];
    float mrow[4], lrow[4];
#pragma unroll
    for (int i = 0; i < 4; i++) {
        mrow[i] = -INFINITY; lrow[i] = 0.f;
#pragma unroll
        for (int j = 0; j < 4; j++) o[i][j] = 0.f;
    }

    const float scale = 0.125f;
    int qr0 = qb * 64 + ty * 4;
    int kc0t = tx * 4;

    for (int kb = 0; kb <= qb; kb++) {
        for (int i = tid; i < 1024; i += 256) {
            int cc = i >> 4, d4 = (i & 15) << 2;
            float4 kv = *(const float4*)(Kbase + (size_t)(kb * 64 + cc) * HD + d4);
            tstore(Ks, d4 + 0, cc, kv.x); tstore(Ks, d4 + 1, cc, kv.y);
            tstore(Ks, d4 + 2, cc, kv.z); tstore(Ks, d4 + 3, cc, kv.w);
            float4 vv = *(const float4*)(Vbase + (size_t)(kb * 64 + cc) * HD + d4);
            *(float4*)&Vs[cc * 64 + d4] = vv;
        }
        __syncthreads();

        float s[4][4];
#pragma unroll
        for (int i = 0; i < 4; i++)
#pragma unroll
            for (int j = 0; j < 4; j++) s[i][j] = 0.f;
#pragma unroll 4
        for (int d = 0; d < 64; d++) {
            float4 qv = *(const float4*)(Qs + d * 64 + (((ty ^ (d >> 2)) & 15) << 2));
            float4 kv = *(const float4*)(Ks + d * 64 + (((tx ^ (d >> 2)) & 15) << 2));
            float qa[4] = {qv.x, qv.y, qv.z, qv.w};
            float ka[4] = {kv.x, kv.y, kv.z, kv.w};
#pragma unroll
            for (int i = 0; i < 4; i++)
#pragma unroll
                for (int j = 0; j < 4; j++)
                    s[i][j] += qa[i] * ka[j];
        }

        int kc0 = kb * 64 + kc0t;
#pragma unroll
        for (int i = 0; i < 4; i++)
#pragma unroll
            for (int j = 0; j < 4; j++) {
                float v = s[i][j] * scale;
                if (kc0 + j > qr0 + i) v = -INFINITY;
                s[i][j] = v;
            }

#pragma unroll
        for (int i = 0; i < 4; i++) {
            float v = fmaxf(fmaxf(s[i][0], s[i][1]), fmaxf(s[i][2], s[i][3]));
            v = fmaxf(v, __shfl_xor_sync(0xffffffffu, v, 8));
            v = fmaxf(v, __shfl_xor_sync(0xffffffffu, v, 4));
            v = fmaxf(v, __shfl_xor_sync(0xffffffffu, v, 2));
            v = fmaxf(v, __shfl_xor_sync(0xffffffffu, v, 1));
            float mnew = fmaxf(mrow[i], v);
            float alpha = __expf(mrow[i] - mnew);
            mrow[i] = mnew;
            float rs = 0.f;
#pragma unroll
            for (int j = 0; j < 4; j++) {
                s[i][j] = __expf(s[i][j] - mnew);
                rs += s[i][j];
            }
            rs += __shfl_xor_sync(0xffffffffu, rs, 8);
            rs += __shfl_xor_sync(0xffffffffu, rs, 4);
            rs += __shfl_xor_sync(0xffffffffu, rs, 2);
            rs += __shfl_xor_sync(0xffffffffu, rs, 1);
            lrow[i] = lrow[i] * alpha + rs;
#pragma unroll
            for (int j = 0; j < 4; j++) o[i][j] *= alpha;
        }

#pragma unroll
        for (int i = 0; i < 4; i++)
#pragma unroll
            for (int j = 0; j < 4; j++)
                tstore(Ps, tx * 4 + j, ty * 4 + i, s[i][j]);
        __syncthreads();

#pragma unroll 4
        for (int cc = 0; cc < 64; cc++) {
            float4 pv = *(const float4*)(Ps + cc * 64 + (((ty ^ (cc >> 2)) & 15) << 2));
            float4 vv = *(const float4*)(Vs + cc * 64 + tx * 4);
            float pa[4] = {pv.x, pv.y, pv.z, pv.w};
            float va[4] = {vv.x, vv.y, vv.z, vv.w};
#pragma unroll
            for (int i = 0; i < 4; i++)
#pragma unroll
                for (int j = 0; j < 4; j++)
                    o[i][j] += pa[i] * va[j];
        }
        __syncthreads();
    }

    int b = bh >> 4, h = bh & 15;
#pragma unroll
    for (int i = 0; i < 4; i++) {
        float inv = 1.0f / lrow[i];
        int t = qb * 64 + ty * 4 + i;
        float* dst = Yg + ((size_t)(b * Tt + t)) * Cc + h * 64 + tx * 4;
        // emit tf32-rounded values: O-projection consumes them as tf32 operands
        *(float4*)dst = make_float4(round_tf32(o[i][0] * inv), round_tf32(o[i][1] * inv),
                                    round_tf32(o[i][2] * inv), round_tf32(o[i][3] * inv));
    }
}

// ---------------------------------------------------------------------------
extern "C" void kernel_launch(void* const* d_in, const int* in_sizes, int n_in,
                              void* d_out, int out_size)
{
    const float* xq = (const float*)d_in[0];
    const float* xk = (const float*)d_in[1];
    const float* xv = (const float*)d_in[2];
    const float* Wq = (const float*)d_in[3];
    const float* Wk = (const float*)d_in[4];
    const float* Wv = (const float*)d_in[5];
    const float* Wo = (const float*)d_in[6];
    const float* bo = (const float*)d_in[7];
    float* out = (float*)d_out;

    float *rxq, *rxk, *rxv, *rWq, *rWk, *rWv, *rWo, *Qp, *Kp, *Vp, *Yp;
    cudaGetSymbolAddress((void**)&rxq, g_rxq);
    cudaGetSymbolAddress((void**)&rxk, g_rxk);
    cudaGetSymbolAddress((void**)&rxv, g_rxv);
    cudaGetSymbolAddress((void**)&rWq, g_rWq);
    cudaGetSymbolAddress((void**)&rWk, g_rWk);
    cudaGetSymbolAddress((void**)&rWv, g_rWv);
    cudaGetSymbolAddress((void**)&rWo, g_rWo);
    cudaGetSymbolAddress((void**)&Qp, g_Q);
    cudaGetSymbolAddress((void**)&Kp, g_K);
    cudaGetSymbolAddress((void**)&Vp, g_V);
    cudaGetSymbolAddress((void**)&Yp, g_Y);

    cudaFuncSetAttribute(gemm_mma, cudaFuncAttributeMaxDynamicSharedMemorySize, GEMM_SMEM);
    cudaFuncSetAttribute(flash_attn, cudaFuncAttributeMaxDynamicSharedMemorySize, 65536);

    const int NX4 = Mrows * Cc / 4;
    const int NW4 = Cc * Cc / 4;
    round_kernel<<<1024, 256>>>((const float4*)xq, (float4*)rxq, NX4);
    round_kernel<<<1024, 256>>>((const float4*)xk, (float4*)rxk, NX4);
    round_kernel<<<1024, 256>>>((const float4*)xv, (float4*)rxv, NX4);
    round_kernel<<<512, 256>>>((const float4*)Wq, (float4*)rWq, NW4);
    round_kernel<<<512, 256>>>((const float4*)Wk, (float4*)rWk, NW4);
    round_kernel<<<512, 256>>>((const float4*)Wv, (float4*)rWv, NW4);
    round_kernel<<<512, 256>>>((const float4*)Wo, (float4*)rWo, NW4);

    dim3 ggrid(Cc / 128, Mrows / 128);   // (8, 64)
    gemm_mma<<<ggrid, 256, GEMM_SMEM>>>(rxq, rWq, nullptr, Qp, 1);
    gemm_mma<<<ggrid, 256, GEMM_SMEM>>>(rxk, rWk, nullptr, Kp, 1);
    gemm_mma<<<ggrid, 256, GEMM_SMEM>>>(rxv, rWv, nullptr, Vp, 1);

    flash_attn<<<dim3(Tt / 64, Bb * Hh), 256, 65536>>>(Qp, Kp, Vp, Yp);

    gemm_mma<<<ggrid, 256, GEMM_SMEM>>>(Yp, rWo, bo, out, 0);
}

// round 4
// speedup vs baseline: 3.1782x; 1.8976x over previous
#include <cuda_runtime.h>
#include <math.h>
#include <stdint.h>

// Problem constants
#define Bb 4
#define Tt 2048
#define Cc 1024
#define Hh 16
#define HD 64
#define Mrows (Bb*Tt)   // 8192
#define GK 1024

// ---------------------------------------------------------------------------
// Helpers
// ---------------------------------------------------------------------------
__device__ __forceinline__ uint32_t smem_u32(const void* p) {
    uint32_t a;
    asm("{ .reg .u64 t; cvta.to.shared.u64 t, %1; cvt.u32.u64 %0, t; }"
        : "=r"(a) : "l"(p));
    return a;
}

__device__ __forceinline__ void cp_async16(uint32_t dst, const void* src) {
    asm volatile("cp.async.cg.shared.global [%0], [%1], 16;"
                 :: "r"(dst), "l"(src) : "memory");
}

__device__ __forceinline__ float round_tf32(float x) {
    uint32_t u;
    asm("cvt.rna.tf32.f32 %0, %1;" : "=r"(u) : "f"(x));
    return __uint_as_float(u);
}
__device__ __forceinline__ uint32_t round_tf32_u(float x) {
    uint32_t u;
    asm("cvt.rna.tf32.f32 %0, %1;" : "=r"(u) : "f"(x));
    return u;
}

// mma.sync m16n8k8 tf32 (base ISA, HMMA fallback on sm_103a)
__device__ __forceinline__ void mma16n8k8(
    float* c, const uint32_t* a, const uint32_t* b)
{
    asm volatile(
        "mma.sync.aligned.m16n8k8.row.col.f32.tf32.tf32.f32 "
        "{%0,%1,%2,%3}, {%4,%5,%6,%7}, {%8,%9}, {%0,%1,%2,%3};"
        : "+f"(c[0]), "+f"(c[1]), "+f"(c[2]), "+f"(c[3])
        : "r"(a[0]), "r"(a[1]), "r"(a[2]), "r"(a[3]),
          "r"(b[0]), "r"(b[1]));
}

// ---------------------------------------------------------------------------
// Scratch (allocation-free: __device__ globals)
// ---------------------------------------------------------------------------
__device__ float g_rxq[(size_t)Mrows*Cc];
__device__ float g_rxk[(size_t)Mrows*Cc];
__device__ float g_rxv[(size_t)Mrows*Cc];
__device__ float g_rWq[(size_t)Cc*Cc];
__device__ float g_rWk[(size_t)Cc*Cc];
__device__ float g_rWv[(size_t)Cc*Cc];
__device__ float g_rWo[(size_t)Cc*Cc];
__device__ float g_Q[(size_t)Bb*Hh*Tt*HD];
__device__ float g_K[(size_t)Bb*Hh*Tt*HD];
__device__ float g_V[(size_t)Bb*Hh*Tt*HD];
__device__ float g_Y[(size_t)Bb*Tt*Cc];

// ---------------------------------------------------------------------------
// RNA-round fp32 -> tf32-valued fp32
// ---------------------------------------------------------------------------
__global__ __launch_bounds__(256) void round_kernel(
    const float4* __restrict__ src, float4* __restrict__ dst, int n4)
{
    int i = blockIdx.x * blockDim.x + threadIdx.x;
    int stride = gridDim.x * blockDim.x;
    for (; i < n4; i += stride) {
        float4 v = src[i];
        v.x = round_tf32(v.x); v.y = round_tf32(v.y);
        v.z = round_tf32(v.z); v.w = round_tf32(v.w);
        dst[i] = v;
    }
}

// ---------------------------------------------------------------------------
// tf32 mma.sync NT GEMM (validated in R3)
// ---------------------------------------------------------------------------
#define PADK 36
#define STGF (128*PADK*2)
#define GEMM_SMEM (2*STGF*4)
#define KTILES (GK/32)

__global__ __launch_bounds__(256, 1) void gemm_mma(
    const float* __restrict__ A, const float* __restrict__ W,
    const float* __restrict__ bias, float* __restrict__ out, int head_layout)
{
    extern __shared__ __align__(16) float dsm[];
    const int tid = threadIdx.x;
    const int wid = tid >> 5, lane = tid & 31;
    const int wm = wid & 1, wn = wid >> 1;
    const int bm = blockIdx.y * 128, bn = blockIdx.x * 128;

    const uint32_t sbase = smem_u32(dsm);
    const int lg = lane >> 2;
    const int lk = lane & 3;

    float c[4][4][4];
#pragma unroll
    for (int i = 0; i < 4; i++)
#pragma unroll
        for (int j = 0; j < 4; j++)
#pragma unroll
            for (int r = 0; r < 4; r++) c[i][j][r] = 0.f;

    const int ch_m = tid >> 3;
    const int ch_k = (tid & 7) << 2;

    {
        uint32_t a_s = sbase, b_s = sbase + 128 * PADK * 4;
#pragma unroll
        for (int i = 0; i < 4; i++) {
            int m = ch_m + i * 32;
            uint32_t so = (uint32_t)(m * PADK + ch_k) * 4;
            cp_async16(a_s + so, A + (size_t)(bm + m) * GK + ch_k);
            cp_async16(b_s + so, W + (size_t)(bn + m) * GK + ch_k);
        }
        asm volatile("cp.async.commit_group;" ::: "memory");
    }

    for (int it = 0; it < KTILES; ++it) {
        if (it + 1 < KTILES) {
            int s = (it + 1) & 1;
            int kt = (it + 1) * 32;
            uint32_t a_s = sbase + s * STGF * 4, b_s = a_s + 128 * PADK * 4;
#pragma unroll
            for (int i = 0; i < 4; i++) {
                int m = ch_m + i * 32;
                uint32_t so = (uint32_t)(m * PADK + ch_k) * 4;
                cp_async16(a_s + so, A + (size_t)(bm + m) * GK + kt + ch_k);
                cp_async16(b_s + so, W + (size_t)(bn + m) * GK + kt + ch_k);
            }
            asm volatile("cp.async.commit_group;" ::: "memory");
            asm volatile("cp.async.wait_group 1;" ::: "memory");
        } else {
            asm volatile("cp.async.wait_group 0;" ::: "memory");
        }
        __syncthreads();

        const float* As = dsm + (it & 1) * STGF;
        const float* Bs = As + 128 * PADK;

#pragma unroll
        for (int kk = 0; kk < 32; kk += 8) {
            uint32_t af[4][4], bf[4][2];
#pragma unroll
            for (int mt = 0; mt < 4; mt++) {
                int r = wm * 64 + mt * 16 + lg;
                af[mt][0] = __float_as_uint(As[r * PADK + kk + lk]);
                af[mt][1] = __float_as_uint(As[(r + 8) * PADK + kk + lk]);
                af[mt][2] = __float_as_uint(As[r * PADK + kk + 4 + lk]);
                af[mt][3] = __float_as_uint(As[(r + 8) * PADK + kk + 4 + lk]);
            }
#pragma unroll
            for (int nt = 0; nt < 4; nt++) {
                int n = wn * 32 + nt * 8 + lg;
                bf[nt][0] = __float_as_uint(Bs[n * PADK + kk + lk]);
                bf[nt][1] = __float_as_uint(Bs[n * PADK + kk + 4 + lk]);
            }
#pragma unroll
            for (int mt = 0; mt < 4; mt++)
#pragma unroll
                for (int nt = 0; nt < 4; nt++)
                    mma16n8k8(c[mt][nt], af[mt], bf[nt]);
        }
        __syncthreads();
    }

#pragma unroll
    for (int mt = 0; mt < 4; mt++) {
        int r0 = bm + wm * 64 + mt * 16 + lg;
#pragma unroll
        for (int nt = 0; nt < 4; nt++) {
            int n = bn + wn * 32 + nt * 8 + lk * 2;
            if (head_layout) {
                int h = n >> 6, d = n & 63;
                int b0 = r0 >> 11, t0 = r0 & (Tt - 1);
                float* dst0 = out + ((size_t)(b0 * Hh + h) * Tt + t0) * HD + d;
                *(float2*)dst0 = make_float2(c[mt][nt][0], c[mt][nt][1]);
                int r1 = r0 + 8;
                int b1 = r1 >> 11, t1 = r1 & (Tt - 1);
                float* dst1 = out + ((size_t)(b1 * Hh + h) * Tt + t1) * HD + d;
                *(float2*)dst1 = make_float2(c[mt][nt][2], c[mt][nt][3]);
            } else {
                float2 bv = bias ? *(const float2*)(bias + n) : make_float2(0.f, 0.f);
                float* dst0 = out + (size_t)r0 * Cc + n;
                *(float2*)dst0 = make_float2(c[mt][nt][0] + bv.x, c[mt][nt][1] + bv.y);
                float* dst1 = out + (size_t)(r0 + 8) * Cc + n;
                *(float2*)dst1 = make_float2(c[mt][nt][2] + bv.x, c[mt][nt][3] + bv.y);
            }
        }
    }
}

// ---------------------------------------------------------------------------
// Tensor-core causal flash attention (tf32 mma.sync).
// CTA: 128 threads (4 warps), 64 query rows; key tiles of 64.
// Warp w owns query rows w*16..w*16+15. Q fragments register-resident.
// Smem: Ks[64][68], Vs[64][68], Ps[64][68] (P rows warp-private).
// ---------------------------------------------------------------------------
#define APAD 68
#define FA_SMEM (3*64*APAD*4)    // 52224 bytes

__global__ __launch_bounds__(128) void flash_mma(
    const float* __restrict__ Qg, const float* __restrict__ Kg,
    const float* __restrict__ Vg, float* __restrict__ Yg)
{
    extern __shared__ __align__(16) float fsm[];
    float* Ks = fsm;
    float* Vs = fsm + 64 * APAD;
    float* Ps = fsm + 2 * 64 * APAD;

    const int tid = threadIdx.x;
    const int w = tid >> 5, lane = tid & 31;
    const int lg = lane >> 2, lk = lane & 3;
    const int qb = blockIdx.x;     // 0..31
    const int bh = blockIdx.y;     // 0..63

    const float* Qbase = Qg + ((size_t)bh * Tt + qb * 64) * HD;
    const float* Kbase = Kg + (size_t)bh * Tt * HD;
    const float* Vbase = Vg + (size_t)bh * Tt * HD;

    // ---- Stage Q tile through Ks buffer, extract register fragments ----
    for (int i = tid; i < 1024; i += 128) {
        int r = i >> 4, c4 = (i & 15) << 2;
        float4 v = *(const float4*)(Qbase + r * HD + c4);
        float* d = Ks + r * APAD + c4;
        d[0] = round_tf32(v.x); d[1] = round_tf32(v.y);
        d[2] = round_tf32(v.z); d[3] = round_tf32(v.w);
    }
    __syncthreads();

    uint32_t qf[8][4];
    {
        const float* r0p = Ks + (w * 16 + lg) * APAD;
        const float* r1p = Ks + (w * 16 + lg + 8) * APAD;
#pragma unroll
        for (int kt = 0; kt < 8; kt++) {
            qf[kt][0] = __float_as_uint(r0p[kt * 8 + lk]);
            qf[kt][1] = __float_as_uint(r1p[kt * 8 + lk]);
            qf[kt][2] = __float_as_uint(r0p[kt * 8 + lk + 4]);
            qf[kt][3] = __float_as_uint(r1p[kt * 8 + lk + 4]);
        }
    }
    __syncthreads();

    float o[8][4];
#pragma unroll
    for (int nt = 0; nt < 8; nt++)
#pragma unroll
        for (int j = 0; j < 4; j++) o[nt][j] = 0.f;
    float m0 = -INFINITY, m1 = -INFINITY, l0 = 0.f, l1 = 0.f;
    const float scale = 0.125f;   // 1/sqrt(64)
    const int lrow0 = w * 16 + lg;     // local row within 64
    const int lrow1 = lrow0 + 8;

    for (int kb = 0; kb <= qb; kb++) {
        // ---- Load K,V tile (rounded to tf32) ----
        for (int i = tid; i < 1024; i += 128) {
            int r = i >> 4, c4 = (i & 15) << 2;
            size_t g = (size_t)(kb * 64 + r) * HD + c4;
            float4 kv = *(const float4*)(Kbase + g);
            float* dk = Ks + r * APAD + c4;
            dk[0] = round_tf32(kv.x); dk[1] = round_tf32(kv.y);
            dk[2] = round_tf32(kv.z); dk[3] = round_tf32(kv.w);
            float4 vv = *(const float4*)(Vbase + g);
            float* dv = Vs + r * APAD + c4;
            dv[0] = round_tf32(vv.x); dv[1] = round_tf32(vv.y);
            dv[2] = round_tf32(vv.z); dv[3] = round_tf32(vv.w);
        }
        __syncthreads();

        // ---- S = Q @ K^T : s[nt][0..3] (rows lrow0/lrow1, cols nt*8+lk*2,+1)
        float s[8][4];
#pragma unroll
        for (int nt = 0; nt < 8; nt++) {
#pragma unroll
            for (int j = 0; j < 4; j++) s[nt][j] = 0.f;
#pragma unroll
            for (int kt = 0; kt < 8; kt++) {
                uint32_t bf[2];
                bf[0] = __float_as_uint(Ks[(nt * 8 + lg) * APAD + kt * 8 + lk]);
                bf[1] = __float_as_uint(Ks[(nt * 8 + lg) * APAD + kt * 8 + lk + 4]);
                mma16n8k8(s[nt], qf[kt], bf);
            }
        }

        // ---- scale + causal mask (diagonal tile only) ----
        if (kb == qb) {
#pragma unroll
            for (int nt = 0; nt < 8; nt++) {
                int c0 = nt * 8 + lk * 2, c1 = c0 + 1;
                s[nt][0] = (c0 > lrow0) ? -INFINITY : s[nt][0] * scale;
                s[nt][1] = (c1 > lrow0) ? -INFINITY : s[nt][1] * scale;
                s[nt][2] = (c0 > lrow1) ? -INFINITY : s[nt][2] * scale;
                s[nt][3] = (c1 > lrow1) ? -INFINITY : s[nt][3] * scale;
            }
        } else {
#pragma unroll
            for (int nt = 0; nt < 8; nt++)
#pragma unroll
                for (int j = 0; j < 4; j++) s[nt][j] *= scale;
        }

        // ---- online softmax (rows lrow0/lrow1; reduce across quad lanes) ----
        float mx0 = -INFINITY, mx1 = -INFINITY;
#pragma unroll
        for (int nt = 0; nt < 8; nt++) {
            mx0 = fmaxf(mx0, fmaxf(s[nt][0], s[nt][1]));
            mx1 = fmaxf(mx1, fmaxf(s[nt][2], s[nt][3]));
        }
        mx0 = fmaxf(mx0, __shfl_xor_sync(0xffffffffu, mx0, 1));
        mx0 = fmaxf(mx0, __shfl_xor_sync(0xffffffffu, mx0, 2));
        mx1 = fmaxf(mx1, __shfl_xor_sync(0xffffffffu, mx1, 1));
        mx1 = fmaxf(mx1, __shfl_xor_sync(0xffffffffu, mx1, 2));

        float mn0 = fmaxf(m0, mx0), mn1 = fmaxf(m1, mx1);
        float a0 = __expf(m0 - mn0), a1 = __expf(m1 - mn1);
        m0 = mn0; m1 = mn1;

        float rs0 = 0.f, rs1 = 0.f;
#pragma unroll
        for (int nt = 0; nt < 8; nt++) {
            s[nt][0] = __expf(s[nt][0] - mn0);
            s[nt][1] = __expf(s[nt][1] - mn0);
            s[nt][2] = __expf(s[nt][2] - mn1);
            s[nt][3] = __expf(s[nt][3] - mn1);
            rs0 += s[nt][0] + s[nt][1];
            rs1 += s[nt][2] + s[nt][3];
        }
        rs0 += __shfl_xor_sync(0xffffffffu, rs0, 1);
        rs0 += __shfl_xor_sync(0xffffffffu, rs0, 2);
        rs1 += __shfl_xor_sync(0xffffffffu, rs1, 1);
        rs1 += __shfl_xor_sync(0xffffffffu, rs1, 2);
        l0 = l0 * a0 + rs0;
        l1 = l1 * a1 + rs1;

#pragma unroll
        for (int nt = 0; nt < 8; nt++) {
            o[nt][0] *= a0; o[nt][1] *= a0;
            o[nt][2] *= a1; o[nt][3] *= a1;
        }

        // ---- write P (tf32-rounded) to warp-private smem rows ----
        {
            float* p0 = Ps + lrow0 * APAD;
            float* p1 = Ps + lrow1 * APAD;
#pragma unroll
            for (int nt = 0; nt < 8; nt++) {
                int cc = nt * 8 + lk * 2;
                p0[cc]     = round_tf32(s[nt][0]);
                p0[cc + 1] = round_tf32(s[nt][1]);
                p1[cc]     = round_tf32(s[nt][2]);
                p1[cc + 1] = round_tf32(s[nt][3]);
            }
        }
        __syncwarp();

        // ---- O += P @ V ----
        uint32_t pf[8][4];
        {
            const float* p0 = Ps + lrow0 * APAD;
            const float* p1 = Ps + lrow1 * APAD;
#pragma unroll
            for (int kt = 0; kt < 8; kt++) {
                pf[kt][0] = __float_as_uint(p0[kt * 8 + lk]);
                pf[kt][1] = __float_as_uint(p1[kt * 8 + lk]);
                pf[kt][2] = __float_as_uint(p0[kt * 8 + lk + 4]);
                pf[kt][3] = __float_as_uint(p1[kt * 8 + lk + 4]);
            }
        }
#pragma unroll
        for (int nt = 0; nt < 8; nt++) {
#pragma unroll
            for (int kt = 0; kt < 8; kt++) {
                uint32_t bf[2];
                bf[0] = __float_as_uint(Vs[(kt * 8 + lk) * APAD + nt * 8 + lg]);
                bf[1] = __float_as_uint(Vs[(kt * 8 + lk + 4) * APAD + nt * 8 + lg]);
                mma16n8k8(o[nt], pf[kt], bf);
            }
        }
        __syncthreads();   // protect Ks/Vs for next tile
    }

    // ---- epilogue: normalize, write Y (tf32-rounded for O-projection) ----
    const int b = bh >> 4, h = bh & 15;
    const float inv0 = 1.0f / l0, inv1 = 1.0f / l1;
    const int t0 = qb * 64 + lrow0, t1 = qb * 64 + lrow1;
#pragma unroll
    for (int nt = 0; nt < 8; nt++) {
        int d = nt * 8 + lk * 2;
        float* dst0 = Yg + ((size_t)(b * Tt + t0)) * Cc + h * 64 + d;
        *(float2*)dst0 = make_float2(round_tf32(o[nt][0] * inv0),
                                     round_tf32(o[nt][1] * inv0));
        float* dst1 = Yg + ((size_t)(b * Tt + t1)) * Cc + h * 64 + d;
        *(float2*)dst1 = make_float2(round_tf32(o[nt][2] * inv1),
                                     round_tf32(o[nt][3] * inv1));
    }
}

// ---------------------------------------------------------------------------
extern "C" void kernel_launch(void* const* d_in, const int* in_sizes, int n_in,
                              void* d_out, int out_size)
{
    const float* xq = (const float*)d_in[0];
    const float* xk = (const float*)d_in[1];
    const float* xv = (const float*)d_in[2];
    const float* Wq = (const float*)d_in[3];
    const float* Wk = (const float*)d_in[4];
    const float* Wv = (const float*)d_in[5];
    const float* Wo = (const float*)d_in[6];
    const float* bo = (const float*)d_in[7];
    float* out = (float*)d_out;

    float *rxq, *rxk, *rxv, *rWq, *rWk, *rWv, *rWo, *Qp, *Kp, *Vp, *Yp;
    cudaGetSymbolAddress((void**)&rxq, g_rxq);
    cudaGetSymbolAddress((void**)&rxk, g_rxk);
    cudaGetSymbolAddress((void**)&rxv, g_rxv);
    cudaGetSymbolAddress((void**)&rWq, g_rWq);
    cudaGetSymbolAddress((void**)&rWk, g_rWk);
    cudaGetSymbolAddress((void**)&rWv, g_rWv);
    cudaGetSymbolAddress((void**)&rWo, g_rWo);
    cudaGetSymbolAddress((void**)&Qp, g_Q);
    cudaGetSymbolAddress((void**)&Kp, g_K);
    cudaGetSymbolAddress((void**)&Vp, g_V);
    cudaGetSymbolAddress((void**)&Yp, g_Y);

    cudaFuncSetAttribute(gemm_mma, cudaFuncAttributeMaxDynamicSharedMemorySize, GEMM_SMEM);
    cudaFuncSetAttribute(flash_mma, cudaFuncAttributeMaxDynamicSharedMemorySize, FA_SMEM);

    const int NX4 = Mrows * Cc / 4;
    const int NW4 = Cc * Cc / 4;
    round_kernel<<<1024, 256>>>((const float4*)xq, (float4*)rxq, NX4);
    round_kernel<<<1024, 256>>>((const float4*)xk, (float4*)rxk, NX4);
    round_kernel<<<1024, 256>>>((const float4*)xv, (float4*)rxv, NX4);
    round_kernel<<<512, 256>>>((const float4*)Wq, (float4*)rWq, NW4);
    round_kernel<<<512, 256>>>((const float4*)Wk, (float4*)rWk, NW4);
    round_kernel<<<512, 256>>>((const float4*)Wv, (float4*)rWv, NW4);
    round_kernel<<<512, 256>>>((const float4*)Wo, (float4*)rWo, NW4);

    dim3 ggrid(Cc / 128, Mrows / 128);   // (8, 64)
    gemm_mma<<<ggrid, 256, GEMM_SMEM>>>(rxq, rWq, nullptr, Qp, 1);
    gemm_mma<<<ggrid, 256, GEMM_SMEM>>>(rxk, rWk, nullptr, Kp, 1);
    gemm_mma<<<ggrid, 256, GEMM_SMEM>>>(rxv, rWv, nullptr, Vp, 1);

    flash_mma<<<dim3(Tt / 64, Bb * Hh), 128, FA_SMEM>>>(Qp, Kp, Vp, Yp);

    gemm_mma<<<ggrid, 256, GEMM_SMEM>>>(Yp, rWo, bo, out, 0);
}

// round 5
// speedup vs baseline: 6.3180x; 1.9879x over previous
#include <cuda_runtime.h>
#include <cuda_fp16.h>
#include <math.h>
#include <stdint.h>

// Problem constants
#define Bb 4
#define Tt 2048
#define Cc 1024
#define Hh 16
#define HD 64
#define Mrows (Bb*Tt)   // 8192
#define GK 1024

// ---------------------------------------------------------------------------
// Helpers
// ---------------------------------------------------------------------------
__device__ __forceinline__ uint32_t smem_u32(const void* p) {
    uint32_t a;
    asm("{ .reg .u64 t; cvta.to.shared.u64 t, %1; cvt.u32.u64 %0, t; }"
        : "=r"(a) : "l"(p));
    return a;
}

__device__ __forceinline__ void cp_async16(uint32_t dst, const void* src) {
    asm volatile("cp.async.cg.shared.global [%0], [%1], 16;"
                 :: "r"(dst), "l"(src) : "memory");
}
#define CP_COMMIT() asm volatile("cp.async.commit_group;" ::: "memory")
#define CP_WAIT0()  asm volatile("cp.async.wait_group 0;" ::: "memory")
#define CP_WAIT1()  asm volatile("cp.async.wait_group 1;" ::: "memory")

// mma.sync m16n8k16 fp16 inputs, fp32 accumulate
__device__ __forceinline__ void mma16n8k16(
    float* c, const uint32_t* a, const uint32_t* b)
{
    asm volatile(
        "mma.sync.aligned.m16n8k16.row.col.f32.f16.f16.f32 "
        "{%0,%1,%2,%3}, {%4,%5,%6,%7}, {%8,%9}, {%0,%1,%2,%3};"
        : "+f"(c[0]), "+f"(c[1]), "+f"(c[2]), "+f"(c[3])
        : "r"(a[0]), "r"(a[1]), "r"(a[2]), "r"(a[3]),
          "r"(b[0]), "r"(b[1]));
}

// ldmatrix x4 transposed (for V B-fragments in P@V)
__device__ __forceinline__ void ldsm_x4_t(uint32_t* r, uint32_t addr) {
    asm volatile(
        "ldmatrix.sync.aligned.m8n8.x4.trans.shared.b16 {%0,%1,%2,%3}, [%4];"
        : "=r"(r[0]), "=r"(r[1]), "=r"(r[2]), "=r"(r[3]) : "r"(addr));
}

// ---------------------------------------------------------------------------
// Scratch (allocation-free: __device__ globals), all fp16 except final stage
// ---------------------------------------------------------------------------
__device__ __half g_hxq[(size_t)Mrows*Cc];
__device__ __half g_hxk[(size_t)Mrows*Cc];
__device__ __half g_hxv[(size_t)Mrows*Cc];
__device__ __half g_hWq[(size_t)Cc*Cc];
__device__ __half g_hWk[(size_t)Cc*Cc];
__device__ __half g_hWv[(size_t)Cc*Cc];
__device__ __half g_hWo[(size_t)Cc*Cc];
__device__ __half g_Q[(size_t)Bb*Hh*Tt*HD];
__device__ __half g_K[(size_t)Bb*Hh*Tt*HD];
__device__ __half g_V[(size_t)Bb*Hh*Tt*HD];
__device__ __half g_Y[(size_t)Bb*Tt*Cc];

// ---------------------------------------------------------------------------
// Batched fp32 -> fp16 convert: one launch handles all 7 tensors
// ---------------------------------------------------------------------------
struct CvtArgs {
    const float4* src[7];
    uint2*        dst[7];
    int           n4[7];
};

__global__ __launch_bounds__(256) void cvt_kernel(CvtArgs a) {
    int j = blockIdx.y;
    const float4* __restrict__ s = a.src[j];
    uint2* __restrict__ d = a.dst[j];
    int n4 = a.n4[j];
    int stride = gridDim.x * blockDim.x;
    for (int i = blockIdx.x * blockDim.x + threadIdx.x; i < n4; i += stride) {
        float4 v = s[i];
        __half2 h0 = __floats2half2_rn(v.x, v.y);
        __half2 h1 = __floats2half2_rn(v.z, v.w);
        uint2 o;
        o.x = *reinterpret_cast<uint32_t*>(&h0);
        o.y = *reinterpret_cast<uint32_t*>(&h1);
        d[i] = o;
    }
}

// ---------------------------------------------------------------------------
// fp16 mma.sync NT GEMM: out[m][n] = sum_k A[m][k]*W[n][k] (+bias)
// BM=128, BN=128, BK=64. 8 warps (2m x 4n), warp tile 64x32.
// Smem rows padded to 72 halves (stride 144B): fragment LDS conflict-free.
// head_layout=1: half output scattered into (B,H,T,64); else fp32+bias.
// ---------------------------------------------------------------------------
#define HPAD 72                 // halves per smem row
#define HROWB 144               // bytes per smem row
#define GTILE (128*HROWB)       // one 128x64 half tile = 18432 B
#define GSTAGE (2*GTILE)        // A + B = 36864 B
#define GEMM_SMEM (2*GSTAGE)    // 73728 B
#define GKT (GK/64)             // 16 iterations

__global__ __launch_bounds__(256, 1) void gemm_mma(
    const __half* __restrict__ A, const __half* __restrict__ W,
    const float* __restrict__ bias, void* __restrict__ outv, int head_layout)
{
    extern __shared__ __align__(16) char dsm[];
    const int tid = threadIdx.x;
    const int wid = tid >> 5, lane = tid & 31;
    const int wm = wid & 1, wn = wid >> 1;
    const int bm = blockIdx.y * 128, bn = blockIdx.x * 128;

    const uint32_t sbase = smem_u32(dsm);
    const int lg = lane >> 2;
    const int lk = lane & 3;

    float c[4][4][4];
#pragma unroll
    for (int i = 0; i < 4; i++)
#pragma unroll
        for (int j = 0; j < 4; j++)
#pragma unroll
            for (int r = 0; r < 4; r++) c[i][j][r] = 0.f;

    // loaders: chunk = tid&7 (16B = 8 halves), rowbase = tid>>3 (0..31), 4 rows
    const int ch = tid & 7;
    const int rb = tid >> 3;

    auto issue_stage = [&](int stage, int k0) {
        uint32_t a_s = sbase + stage * GSTAGE;
        uint32_t b_s = a_s + GTILE;
#pragma unroll
        for (int i = 0; i < 4; i++) {
            int r = rb + i * 32;
            uint32_t so = (uint32_t)r * HROWB + ch * 16;
            cp_async16(a_s + so, A + (size_t)(bm + r) * GK + k0 + ch * 8);
            cp_async16(b_s + so, W + (size_t)(bn + r) * GK + k0 + ch * 8);
        }
        CP_COMMIT();
    };

    issue_stage(0, 0);

    for (int it = 0; it < GKT; ++it) {
        if (it + 1 < GKT) {
            issue_stage((it + 1) & 1, (it + 1) * 64);
            CP_WAIT1();
        } else {
            CP_WAIT0();
        }
        __syncthreads();

        const char* As = dsm + (it & 1) * GSTAGE;
        const char* Bs = As + GTILE;

#pragma unroll
        for (int ks = 0; ks < 4; ks++) {   // 4 x k16 = BK 64
            uint32_t af[4][4], bf[4][2];
#pragma unroll
            for (int mt = 0; mt < 4; mt++) {
                int r = wm * 64 + mt * 16 + lg;
                const char* p0 = As + r * HROWB + 4 * lk + 32 * ks;
                const char* p1 = As + (r + 8) * HROWB + 4 * lk + 32 * ks;
                af[mt][0] = *(const uint32_t*)p0;
                af[mt][1] = *(const uint32_t*)p1;
                af[mt][2] = *(const uint32_t*)(p0 + 16);
                af[mt][3] = *(const uint32_t*)(p1 + 16);
            }
#pragma unroll
            for (int nt = 0; nt < 4; nt++) {
                int n = wn * 32 + nt * 8 + lg;
                const char* p = Bs + n * HROWB + 4 * lk + 32 * ks;
                bf[nt][0] = *(const uint32_t*)p;
                bf[nt][1] = *(const uint32_t*)(p + 16);
            }
#pragma unroll
            for (int mt = 0; mt < 4; mt++)
#pragma unroll
                for (int nt = 0; nt < 4; nt++)
                    mma16n8k16(c[mt][nt], af[mt], bf[nt]);
        }
        __syncthreads();
    }

    // Epilogue
#pragma unroll
    for (int mt = 0; mt < 4; mt++) {
        int r0 = bm + wm * 64 + mt * 16 + lg;
#pragma unroll
        for (int nt = 0; nt < 4; nt++) {
            int n = bn + wn * 32 + nt * 8 + lk * 2;
            if (head_layout) {
                __half* out = (__half*)outv;
                int h = n >> 6, d = n & 63;
                int b0 = r0 >> 11, t0 = r0 & (Tt - 1);
                __half2 h01 = __floats2half2_rn(c[mt][nt][0], c[mt][nt][1]);
                *(__half2*)(out + ((size_t)(b0 * Hh + h) * Tt + t0) * HD + d) = h01;
                int r1 = r0 + 8;
                int b1 = r1 >> 11, t1 = r1 & (Tt - 1);
                __half2 h23 = __floats2half2_rn(c[mt][nt][2], c[mt][nt][3]);
                *(__half2*)(out + ((size_t)(b1 * Hh + h) * Tt + t1) * HD + d) = h23;
            } else {
                float* out = (float*)outv;
                float2 bv = *(const float2*)(bias + n);
                *(float2*)(out + (size_t)r0 * Cc + n) =
                    make_float2(c[mt][nt][0] + bv.x, c[mt][nt][1] + bv.y);
                *(float2*)(out + (size_t)(r0 + 8) * Cc + n) =
                    make_float2(c[mt][nt][2] + bv.x, c[mt][nt][3] + bv.y);
            }
        }
    }
}

// ---------------------------------------------------------------------------
// fp16 tensor-core causal flash attention.
// CTA: 128 threads (4 warps), 64 query rows; key tiles of 64, double-buffered.
// Smem: K/V tiles x2 stages + P tile; rows padded to 72 halves.
// ---------------------------------------------------------------------------
#define FT_BYTES (64*HROWB)       // 9216 B per 64x64 half tile
#define FA_SMEM (5*FT_BYTES)      // 2 stages x (K,V) + P = 46080 B

__global__ __launch_bounds__(128) void flash_mma(
    const __half* __restrict__ Qg, const __half* __restrict__ Kg,
    const __half* __restrict__ Vg, __half* __restrict__ Yg)
{
    extern __shared__ __align__(16) char fsm[];
    // stage s: K at s*2*FT, V at s*2*FT + FT; P at 4*FT
    char* Ps = fsm + 4 * FT_BYTES;
    const uint32_t sb = smem_u32(fsm);
    const uint32_t ps_b = sb + 4 * FT_BYTES;

    const int tid = threadIdx.x;
    const int w = tid >> 5, lane = tid & 31;
    const int lg = lane >> 2, lk = lane & 3;
    const int qb = blockIdx.x;     // 0..31
    const int bh = blockIdx.y;     // 0..63

    const __half* Qbase = Qg + ((size_t)bh * Tt + qb * 64) * HD;
    const __half* Kbase = Kg + (size_t)bh * Tt * HD;
    const __half* Vbase = Vg + (size_t)bh * Tt * HD;

    const int lrow0 = w * 16 + lg;
    const int lrow1 = lrow0 + 8;

    // loader mapping: chunk = tid&7 (16B), rowbase = tid>>3 (0..15), 4 rows
    const int ch = tid & 7;
    const int rb = tid >> 3;

    // ---- stage Q through P buffer ----
#pragma unroll
    for (int i = 0; i < 4; i++) {
        int r = rb + i * 16;
        cp_async16(ps_b + (uint32_t)r * HROWB + ch * 16,
                   Qbase + (size_t)r * HD + ch * 8);
    }
    CP_COMMIT();

    auto issue_tile = [&](int kb) {
        uint32_t k_s = sb + (kb & 1) * 2 * FT_BYTES;
        uint32_t v_s = k_s + FT_BYTES;
#pragma unroll
        for (int i = 0; i < 4; i++) {
            int r = rb + i * 16;
            uint32_t so = (uint32_t)r * HROWB + ch * 16;
            size_t g = (size_t)(kb * 64 + r) * HD + ch * 8;
            cp_async16(k_s + so, Kbase + g);
            cp_async16(v_s + so, Vbase + g);
        }
        CP_COMMIT();
    };

    issue_tile(0);

    // Q fragments: wait for Q group (1 pending allowed = tile0)
    CP_WAIT1();
    __syncthreads();
    uint32_t qf[4][4];
    {
        const char* p0 = Ps + lrow0 * HROWB;
        const char* p1 = Ps + lrow1 * HROWB;
#pragma unroll
        for (int kt = 0; kt < 4; kt++) {
            qf[kt][0] = *(const uint32_t*)(p0 + 4 * lk + 32 * kt);
            qf[kt][1] = *(const uint32_t*)(p1 + 4 * lk + 32 * kt);
            qf[kt][2] = *(const uint32_t*)(p0 + 4 * lk + 32 * kt + 16);
            qf[kt][3] = *(const uint32_t*)(p1 + 4 * lk + 32 * kt + 16);
        }
    }
    __syncthreads();   // P buffer free for reuse

    float o[8][4];
#pragma unroll
    for (int nt = 0; nt < 8; nt++)
#pragma unroll
        for (int j = 0; j < 4; j++) o[nt][j] = 0.f;
    float m0 = -INFINITY, m1 = -INFINITY, l0 = 0.f, l1 = 0.f;
    const float scale = 0.125f;   // 1/sqrt(64)

    for (int kb = 0; kb <= qb; kb++) {
        if (kb + 1 <= qb) {
            issue_tile(kb + 1);
            CP_WAIT1();
        } else {
            CP_WAIT0();
        }
        __syncthreads();

        const char* Ks = fsm + (kb & 1) * 2 * FT_BYTES;
        const uint32_t vs_b = sb + (kb & 1) * 2 * FT_BYTES + FT_BYTES;

        // ---- S = Q @ K^T ----
        float s[8][4];
#pragma unroll
        for (int nt = 0; nt < 8; nt++) {
#pragma unroll
            for (int j = 0; j < 4; j++) s[nt][j] = 0.f;
            const char* kp = Ks + (nt * 8 + lg) * HROWB + 4 * lk;
#pragma unroll
            for (int kt = 0; kt < 4; kt++) {
                uint32_t bf[2];
                bf[0] = *(const uint32_t*)(kp + 32 * kt);
                bf[1] = *(const uint32_t*)(kp + 32 * kt + 16);
                mma16n8k16(s[nt], qf[kt], bf);
            }
        }

        // ---- scale + causal mask (diagonal tile only) ----
        if (kb == qb) {
#pragma unroll
            for (int nt = 0; nt < 8; nt++) {
                int c0 = nt * 8 + lk * 2, c1 = c0 + 1;
                s[nt][0] = (c0 > lrow0) ? -INFINITY : s[nt][0] * scale;
                s[nt][1] = (c1 > lrow0) ? -INFINITY : s[nt][1] * scale;
                s[nt][2] = (c0 > lrow1) ? -INFINITY : s[nt][2] * scale;
                s[nt][3] = (c1 > lrow1) ? -INFINITY : s[nt][3] * scale;
            }
        } else {
#pragma unroll
            for (int nt = 0; nt < 8; nt++)
#pragma unroll
                for (int j = 0; j < 4; j++) s[nt][j] *= scale;
        }

        // ---- online softmax ----
        float mx0 = -INFINITY, mx1 = -INFINITY;
#pragma unroll
        for (int nt = 0; nt < 8; nt++) {
            mx0 = fmaxf(mx0, fmaxf(s[nt][0], s[nt][1]));
            mx1 = fmaxf(mx1, fmaxf(s[nt][2], s[nt][3]));
        }
        mx0 = fmaxf(mx0, __shfl_xor_sync(0xffffffffu, mx0, 1));
        mx0 = fmaxf(mx0, __shfl_xor_sync(0xffffffffu, mx0, 2));
        mx1 = fmaxf(mx1, __shfl_xor_sync(0xffffffffu, mx1, 1));
        mx1 = fmaxf(mx1, __shfl_xor_sync(0xffffffffu, mx1, 2));

        float mn0 = fmaxf(m0, mx0), mn1 = fmaxf(m1, mx1);
        float a0 = __expf(m0 - mn0), a1 = __expf(m1 - mn1);
        m0 = mn0; m1 = mn1;

        float rs0 = 0.f, rs1 = 0.f;
#pragma unroll
        for (int nt = 0; nt < 8; nt++) {
            s[nt][0] = __expf(s[nt][0] - mn0);
            s[nt][1] = __expf(s[nt][1] - mn0);
            s[nt][2] = __expf(s[nt][2] - mn1);
            s[nt][3] = __expf(s[nt][3] - mn1);
            rs0 += s[nt][0] + s[nt][1];
            rs1 += s[nt][2] + s[nt][3];
        }
        rs0 += __shfl_xor_sync(0xffffffffu, rs0, 1);
        rs0 += __shfl_xor_sync(0xffffffffu, rs0, 2);
        rs1 += __shfl_xor_sync(0xffffffffu, rs1, 1);
        rs1 += __shfl_xor_sync(0xffffffffu, rs1, 2);
        l0 = l0 * a0 + rs0;
        l1 = l1 * a1 + rs1;

#pragma unroll
        for (int nt = 0; nt < 8; nt++) {
            o[nt][0] *= a0; o[nt][1] *= a0;
            o[nt][2] *= a1; o[nt][3] *= a1;
        }

        // ---- write P (fp16) to warp-private smem rows ----
        {
            char* p0 = Ps + lrow0 * HROWB;
            char* p1 = Ps + lrow1 * HROWB;
#pragma unroll
            for (int nt = 0; nt < 8; nt++) {
                int off = nt * 16 + 4 * lk;
                *(__half2*)(p0 + off) = __floats2half2_rn(s[nt][0], s[nt][1]);
                *(__half2*)(p1 + off) = __floats2half2_rn(s[nt][2], s[nt][3]);
            }
        }
        __syncwarp();

        // ---- P fragments ----
        uint32_t pf[4][4];
        {
            const char* p0 = Ps + lrow0 * HROWB;
            const char* p1 = Ps + lrow1 * HROWB;
#pragma unroll
            for (int kt = 0; kt < 4; kt++) {
                pf[kt][0] = *(const uint32_t*)(p0 + 4 * lk + 32 * kt);
                pf[kt][1] = *(const uint32_t*)(p1 + 4 * lk + 32 * kt);
                pf[kt][2] = *(const uint32_t*)(p0 + 4 * lk + 32 * kt + 16);
                pf[kt][3] = *(const uint32_t*)(p1 + 4 * lk + 32 * kt + 16);
            }
        }

        // ---- O += P @ V  (V B-fragments via ldmatrix.x4.trans) ----
#pragma unroll
        for (int nt = 0; nt < 8; nt++) {
#pragma unroll
            for (int g = 0; g < 2; g++) {
                uint32_t vb[4];
                // lanes supply addresses of stored rows k = 32g + lane
                ldsm_x4_t(vb, vs_b + (uint32_t)(32 * g + lane) * HROWB + nt * 16);
                mma16n8k16(o[nt], pf[2 * g], vb);
                mma16n8k16(o[nt], pf[2 * g + 1], vb + 2);
            }
        }
        __syncthreads();   // protect K/V stage for next issue
    }

    // ---- epilogue: normalize, write Y (fp16) ----
    const int b = bh >> 4, h = bh & 15;
    const float inv0 = 1.0f / l0, inv1 = 1.0f / l1;
    const int t0 = qb * 64 + lrow0, t1 = qb * 64 + lrow1;
    __half* dst0 = Yg + ((size_t)(b * Tt + t0)) * Cc + h * 64;
    __half* dst1 = Yg + ((size_t)(b * Tt + t1)) * Cc + h * 64;
#pragma unroll
    for (int nt = 0; nt < 8; nt++) {
        int d = nt * 8 + lk * 2;
        *(__half2*)(dst0 + d) = __floats2half2_rn(o[nt][0] * inv0, o[nt][1] * inv0);
        *(__half2*)(dst1 + d) = __floats2half2_rn(o[nt][2] * inv1, o[nt][3] * inv1);
    }
}

// ---------------------------------------------------------------------------
extern "C" void kernel_launch(void* const* d_in, const int* in_sizes, int n_in,
                              void* d_out, int out_size)
{
    const float* xq = (const float*)d_in[0];
    const float* xk = (const float*)d_in[1];
    const float* xv = (const float*)d_in[2];
    const float* Wq = (const float*)d_in[3];
    const float* Wk = (const float*)d_in[4];
    const float* Wv = (const float*)d_in[5];
    const float* Wo = (const float*)d_in[6];
    const float* bo = (const float*)d_in[7];
    float* out = (float*)d_out;

    __half *hxq, *hxk, *hxv, *hWq, *hWk, *hWv, *hWo, *Qp, *Kp, *Vp, *Yp;
    cudaGetSymbolAddress((void**)&hxq, g_hxq);
    cudaGetSymbolAddress((void**)&hxk, g_hxk);
    cudaGetSymbolAddress((void**)&hxv, g_hxv);
    cudaGetSymbolAddress((void**)&hWq, g_hWq);
    cudaGetSymbolAddress((void**)&hWk, g_hWk);
    cudaGetSymbolAddress((void**)&hWv, g_hWv);
    cudaGetSymbolAddress((void**)&hWo, g_hWo);
    cudaGetSymbolAddress((void**)&Qp, g_Q);
    cudaGetSymbolAddress((void**)&Kp, g_K);
    cudaGetSymbolAddress((void**)&Vp, g_V);
    cudaGetSymbolAddress((void**)&Yp, g_Y);

    cudaFuncSetAttribute(gemm_mma, cudaFuncAttributeMaxDynamicSharedMemorySize, GEMM_SMEM);
    cudaFuncSetAttribute(flash_mma, cudaFuncAttributeMaxDynamicSharedMemorySize, FA_SMEM);

    CvtArgs ca;
    const int NX4 = Mrows * Cc / 4;
    const int NW4 = Cc * Cc / 4;
    ca.src[0] = (const float4*)xq; ca.dst[0] = (uint2*)hxq; ca.n4[0] = NX4;
    ca.src[1] = (const float4*)xk; ca.dst[1] = (uint2*)hxk; ca.n4[1] = NX4;
    ca.src[2] = (const float4*)xv; ca.dst[2] = (uint2*)hxv; ca.n4[2] = NX4;
    ca.src[3] = (const float4*)Wq; ca.dst[3] = (uint2*)hWq; ca.n4[3] = NW4;
    ca.src[4] = (const float4*)Wk; ca.dst[4] = (uint2*)hWk; ca.n4[4] = NW4;
    ca.src[5] = (const float4*)Wv; ca.dst[5] = (uint2*)hWv; ca.n4[5] = NW4;
    ca.src[6] = (const float4*)Wo; ca.dst[6] = (uint2*)hWo; ca.n4[6] = NW4;
    cvt_kernel<<<dim3(1024, 7), 256>>>(ca);

    dim3 ggrid(Cc / 128, Mrows / 128);   // (8, 64)
    gemm_mma<<<ggrid, 256, GEMM_SMEM>>>(hxq, hWq, nullptr, Qp, 1);
    gemm_mma<<<ggrid, 256, GEMM_SMEM>>>(hxk, hWk, nullptr, Kp, 1);
    gemm_mma<<<ggrid, 256, GEMM_SMEM>>>(hxv, hWv, nullptr, Vp, 1);

    flash_mma<<<dim3(Tt / 64, Bb * Hh), 128, FA_SMEM>>>(Qp, Kp, Vp, Yp);

    gemm_mma<<<ggrid, 256, GEMM_SMEM>>>(Yp, hWo, bo, out, 0);
}

// round 6
// speedup vs baseline: 6.9937x; 1.1069x over previous
#include <cuda_runtime.h>
#include <cuda_fp16.h>
#include <math.h>
#include <stdint.h>

// Problem constants
#define Bb 4
#define Tt 2048
#define Cc 1024
#define Hh 16
#define HD 64
#define Mrows (Bb*Tt)   // 8192
#define GK 1024

// ---------------------------------------------------------------------------
// Helpers
// ---------------------------------------------------------------------------
__device__ __forceinline__ uint32_t smem_u32(const void* p) {
    uint32_t a;
    asm("{ .reg .u64 t; cvta.to.shared.u64 t, %1; cvt.u32.u64 %0, t; }"
        : "=r"(a) : "l"(p));
    return a;
}

__device__ __forceinline__ void cp_async16(uint32_t dst, const void* src) {
    asm volatile("cp.async.cg.shared.global [%0], [%1], 16;"
                 :: "r"(dst), "l"(src) : "memory");
}
#define CP_COMMIT() asm volatile("cp.async.commit_group;" ::: "memory")
#define CP_WAIT0()  asm volatile("cp.async.wait_group 0;" ::: "memory")
#define CP_WAIT1()  asm volatile("cp.async.wait_group 1;" ::: "memory")

// mma.sync m16n8k16 fp16 inputs, fp32 accumulate
__device__ __forceinline__ void mma16n8k16(
    float* c, const uint32_t* a, const uint32_t* b)
{
    asm volatile(
        "mma.sync.aligned.m16n8k16.row.col.f32.f16.f16.f32 "
        "{%0,%1,%2,%3}, {%4,%5,%6,%7}, {%8,%9}, {%0,%1,%2,%3};"
        : "+f"(c[0]), "+f"(c[1]), "+f"(c[2]), "+f"(c[3])
        : "r"(a[0]), "r"(a[1]), "r"(a[2]), "r"(a[3]),
          "r"(b[0]), "r"(b[1]));
}

// ldmatrix x4 (non-transposed) and x4 transposed
__device__ __forceinline__ void ldsm_x4(uint32_t* r, uint32_t addr) {
    asm volatile(
        "ldmatrix.sync.aligned.m8n8.x4.shared.b16 {%0,%1,%2,%3}, [%4];"
        : "=r"(r[0]), "=r"(r[1]), "=r"(r[2]), "=r"(r[3]) : "r"(addr));
}
__device__ __forceinline__ void ldsm_x4_t(uint32_t* r, uint32_t addr) {
    asm volatile(
        "ldmatrix.sync.aligned.m8n8.x4.trans.shared.b16 {%0,%1,%2,%3}, [%4];"
        : "=r"(r[0]), "=r"(r[1]), "=r"(r[2]), "=r"(r[3]) : "r"(addr));
}

// ---------------------------------------------------------------------------
// Scratch (allocation-free: __device__ globals)
// ---------------------------------------------------------------------------
__device__ __half g_hxq[(size_t)Mrows*Cc];
__device__ __half g_hxk[(size_t)Mrows*Cc];
__device__ __half g_hxv[(size_t)Mrows*Cc];
__device__ __half g_hWq[(size_t)Cc*Cc];
__device__ __half g_hWk[(size_t)Cc*Cc];
__device__ __half g_hWv[(size_t)Cc*Cc];
__device__ __half g_hWo[(size_t)Cc*Cc];
__device__ __half g_Q[(size_t)Bb*Hh*Tt*HD];
__device__ __half g_K[(size_t)Bb*Hh*Tt*HD];
__device__ __half g_V[(size_t)Bb*Hh*Tt*HD];
__device__ __half g_Y[(size_t)Bb*Tt*Cc];

// ---------------------------------------------------------------------------
// Batched fp32 -> fp16 convert
// ---------------------------------------------------------------------------
struct CvtArgs {
    const float4* src[7];
    uint2*        dst[7];
    int           n4[7];
};

__global__ __launch_bounds__(256) void cvt_kernel(CvtArgs a) {
    int j = blockIdx.y;
    const float4* __restrict__ s = a.src[j];
    uint2* __restrict__ d = a.dst[j];
    int n4 = a.n4[j];
    int stride = gridDim.x * blockDim.x;
    for (int i = blockIdx.x * blockDim.x + threadIdx.x; i < n4; i += stride) {
        float4 v = s[i];
        __half2 h0 = __floats2half2_rn(v.x, v.y);
        __half2 h1 = __floats2half2_rn(v.z, v.w);
        uint2 o;
        o.x = *reinterpret_cast<uint32_t*>(&h0);
        o.y = *reinterpret_cast<uint32_t*>(&h1);
        d[i] = o;
    }
}

// ---------------------------------------------------------------------------
// GEMM core: BM=128, BN=128, BK=64, 8 warps (2m x 4n), warp tile 64x32.
// ldmatrix fragment loads; smem rows 72 halves (144B) -> conflict-free.
// ---------------------------------------------------------------------------
#define HROWB 144               // bytes per smem row (72 halves)
#define GTILE (128*HROWB)       // 18432 B
#define GSTAGE (2*GTILE)        // 36864 B
#define GEMM_SMEM (2*GSTAGE)    // 73728 B
#define GKT (GK/64)             // 16

__device__ __forceinline__ void gemm_core(
    const __half* __restrict__ A, const __half* __restrict__ W,
    int bm, int bn, uint32_t sbase,
    int tid, int wm, int wn, int lane, float c[4][4][4])
{
#pragma unroll
    for (int i = 0; i < 4; i++)
#pragma unroll
        for (int j = 0; j < 4; j++)
#pragma unroll
            for (int r = 0; r < 4; r++) c[i][j][r] = 0.f;

    const int ch = tid & 7;
    const int rb = tid >> 3;
    // ldmatrix lane addressing: row = lane&15, halfsel = lane>>4
    const uint32_t lrow = (uint32_t)(lane & 15) * HROWB + ((lane >> 4) << 4);

    auto issue_stage = [&](int stage, int k0) {
        uint32_t a_s = sbase + stage * GSTAGE;
        uint32_t b_s = a_s + GTILE;
#pragma unroll
        for (int i = 0; i < 4; i++) {
            int r = rb + i * 32;
            uint32_t so = (uint32_t)r * HROWB + ch * 16;
            cp_async16(a_s + so, A + (size_t)(bm + r) * GK + k0 + ch * 8);
            cp_async16(b_s + so, W + (size_t)(bn + r) * GK + k0 + ch * 8);
        }
        CP_COMMIT();
    };

    issue_stage(0, 0);

    for (int it = 0; it < GKT; ++it) {
        if (it + 1 < GKT) {
            issue_stage((it + 1) & 1, (it + 1) * 64);
            CP_WAIT1();
        } else {
            CP_WAIT0();
        }
        __syncthreads();

        uint32_t as_b = sbase + (it & 1) * GSTAGE;
        uint32_t bs_b = as_b + GTILE;

#pragma unroll
        for (int ks = 0; ks < 4; ks++) {
            uint32_t af[4][4], bf[2][4];
#pragma unroll
            for (int mt = 0; mt < 4; mt++)
                ldsm_x4(af[mt],
                        as_b + (uint32_t)(wm * 64 + mt * 16) * HROWB + lrow + ks * 32);
#pragma unroll
            for (int pr = 0; pr < 2; pr++)
                ldsm_x4(bf[pr],
                        bs_b + (uint32_t)(wn * 32 + pr * 16) * HROWB + lrow + ks * 32);
#pragma unroll
            for (int mt = 0; mt < 4; mt++)
#pragma unroll
                for (int nt = 0; nt < 4; nt++) {
                    // nt pair pr=nt>>1; even nt -> {r0,r2}, odd -> {r1,r3}
                    uint32_t b2[2];
                    b2[0] = bf[nt >> 1][nt & 1];
                    b2[1] = bf[nt >> 1][(nt & 1) + 2];
                    mma16n8k16(c[mt][nt], af[mt], b2);
                }
        }
        __syncthreads();
    }
}

// Merged Q/K/V projection: grid.z selects which GEMM. fp16 head-layout out.
struct QKVArgs {
    const __half* A[3];
    const __half* W[3];
    __half*       out[3];
};

__global__ __launch_bounds__(256, 2) void qkv_gemm(QKVArgs args)
{
    extern __shared__ __align__(16) char dsm[];
    const int tid = threadIdx.x;
    const int wid = tid >> 5, lane = tid & 31;
    const int wm = wid & 1, wn = wid >> 1;
    const int bm = blockIdx.y * 128, bn = blockIdx.x * 128;
    const int g = blockIdx.z;
    const int lg = lane >> 2, lk = lane & 3;

    float c[4][4][4];
    gemm_core(args.A[g], args.W[g], bm, bn, smem_u32(dsm),
              tid, wm, wn, lane, c);

    __half* out = args.out[g];
#pragma unroll
    for (int mt = 0; mt < 4; mt++) {
        int r0 = bm + wm * 64 + mt * 16 + lg;
#pragma unroll
        for (int nt = 0; nt < 4; nt++) {
            int n = bn + wn * 32 + nt * 8 + lk * 2;
            int h = n >> 6, d = n & 63;
            int b0 = r0 >> 11, t0 = r0 & (Tt - 1);
            *(__half2*)(out + ((size_t)(b0 * Hh + h) * Tt + t0) * HD + d) =
                __floats2half2_rn(c[mt][nt][0], c[mt][nt][1]);
            int r1 = r0 + 8;
            int b1 = r1 >> 11, t1 = r1 & (Tt - 1);
            *(__half2*)(out + ((size_t)(b1 * Hh + h) * Tt + t1) * HD + d) =
                __floats2half2_rn(c[mt][nt][2], c[mt][nt][3]);
        }
    }
}

// O-projection: fp32 out + bias
__global__ __launch_bounds__(256, 2) void oproj_gemm(
    const __half* __restrict__ A, const __half* __restrict__ W,
    const float* __restrict__ bias, float* __restrict__ out)
{
    extern __shared__ __align__(16) char dsm[];
    const int tid = threadIdx.x;
    const int wid = tid >> 5, lane = tid & 31;
    const int wm = wid & 1, wn = wid >> 1;
    const int bm = blockIdx.y * 128, bn = blockIdx.x * 128;
    const int lg = lane >> 2, lk = lane & 3;

    float c[4][4][4];
    gemm_core(A, W, bm, bn, smem_u32(dsm), tid, wm, wn, lane, c);

#pragma unroll
    for (int mt = 0; mt < 4; mt++) {
        int r0 = bm + wm * 64 + mt * 16 + lg;
#pragma unroll
        for (int nt = 0; nt < 4; nt++) {
            int n = bn + wn * 32 + nt * 8 + lk * 2;
            float2 bv = *(const float2*)(bias + n);
            *(float2*)(out + (size_t)r0 * Cc + n) =
                make_float2(c[mt][nt][0] + bv.x, c[mt][nt][1] + bv.y);
            *(float2*)(out + (size_t)(r0 + 8) * Cc + n) =
                make_float2(c[mt][nt][2] + bv.x, c[mt][nt][3] + bv.y);
        }
    }
}

// ---------------------------------------------------------------------------
// fp16 tensor-core causal flash attention (validated R5, unchanged)
// ---------------------------------------------------------------------------
#define FT_BYTES (64*HROWB)       // 9216 B
#define FA_SMEM (5*FT_BYTES)      // 46080 B

__global__ __launch_bounds__(128) void flash_mma(
    const __half* __restrict__ Qg, const __half* __restrict__ Kg,
    const __half* __restrict__ Vg, __half* __restrict__ Yg)
{
    extern __shared__ __align__(16) char fsm[];
    char* Ps = fsm + 4 * FT_BYTES;
    const uint32_t sb = smem_u32(fsm);
    const uint32_t ps_b = sb + 4 * FT_BYTES;

    const int tid = threadIdx.x;
    const int w = tid >> 5, lane = tid & 31;
    const int lg = lane >> 2, lk = lane & 3;
    const int qb = blockIdx.x;
    const int bh = blockIdx.y;

    const __half* Qbase = Qg + ((size_t)bh * Tt + qb * 64) * HD;
    const __half* Kbase = Kg + (size_t)bh * Tt * HD;
    const __half* Vbase = Vg + (size_t)bh * Tt * HD;

    const int lrow0 = w * 16 + lg;
    const int lrow1 = lrow0 + 8;

    const int ch = tid & 7;
    const int rb = tid >> 3;

#pragma unroll
    for (int i = 0; i < 4; i++) {
        int r = rb + i * 16;
        cp_async16(ps_b + (uint32_t)r * HROWB + ch * 16,
                   Qbase + (size_t)r * HD + ch * 8);
    }
    CP_COMMIT();

    auto issue_tile = [&](int kb) {
        uint32_t k_s = sb + (kb & 1) * 2 * FT_BYTES;
        uint32_t v_s = k_s + FT_BYTES;
#pragma unroll
        for (int i = 0; i < 4; i++) {
            int r = rb + i * 16;
            uint32_t so = (uint32_t)r * HROWB + ch * 16;
            size_t g = (size_t)(kb * 64 + r) * HD + ch * 8;
            cp_async16(k_s + so, Kbase + g);
            cp_async16(v_s + so, Vbase + g);
        }
        CP_COMMIT();
    };

    issue_tile(0);

    CP_WAIT1();
    __syncthreads();
    uint32_t qf[4][4];
    {
        const char* p0 = (const char*)fsm + 4 * FT_BYTES + lrow0 * HROWB;
        const char* p1 = (const char*)fsm + 4 * FT_BYTES + lrow1 * HROWB;
#pragma unroll
        for (int kt = 0; kt < 4; kt++) {
            qf[kt][0] = *(const uint32_t*)(p0 + 4 * lk + 32 * kt);
            qf[kt][1] = *(const uint32_t*)(p1 + 4 * lk + 32 * kt);
            qf[kt][2] = *(const uint32_t*)(p0 + 4 * lk + 32 * kt + 16);
            qf[kt][3] = *(const uint32_t*)(p1 + 4 * lk + 32 * kt + 16);
        }
    }
    __syncthreads();

    float o[8][4];
#pragma unroll
    for (int nt = 0; nt < 8; nt++)
#pragma unroll
        for (int j = 0; j < 4; j++) o[nt][j] = 0.f;
    float m0 = -INFINITY, m1 = -INFINITY, l0 = 0.f, l1 = 0.f;
    const float scale = 0.125f;

    for (int kb = 0; kb <= qb; kb++) {
        if (kb + 1 <= qb) {
            issue_tile(kb + 1);
            CP_WAIT1();
        } else {
            CP_WAIT0();
        }
        __syncthreads();

        const char* Ks = fsm + (kb & 1) * 2 * FT_BYTES;
        const uint32_t vs_b = sb + (kb & 1) * 2 * FT_BYTES + FT_BYTES;

        float s[8][4];
#pragma unroll
        for (int nt = 0; nt < 8; nt++) {
#pragma unroll
            for (int j = 0; j < 4; j++) s[nt][j] = 0.f;
            const char* kp = Ks + (nt * 8 + lg) * HROWB + 4 * lk;
#pragma unroll
            for (int kt = 0; kt < 4; kt++) {
                uint32_t bfr[2];
                bfr[0] = *(const uint32_t*)(kp + 32 * kt);
                bfr[1] = *(const uint32_t*)(kp + 32 * kt + 16);
                mma16n8k16(s[nt], qf[kt], bfr);
            }
        }

        if (kb == qb) {
#pragma unroll
            for (int nt = 0; nt < 8; nt++) {
                int c0 = nt * 8 + lk * 2, c1 = c0 + 1;
                s[nt][0] = (c0 > lrow0) ? -INFINITY : s[nt][0] * scale;
                s[nt][1] = (c1 > lrow0) ? -INFINITY : s[nt][1] * scale;
                s[nt][2] = (c0 > lrow1) ? -INFINITY : s[nt][2] * scale;
                s[nt][3] = (c1 > lrow1) ? -INFINITY : s[nt][3] * scale;
            }
        } else {
#pragma unroll
            for (int nt = 0; nt < 8; nt++)
#pragma unroll
                for (int j = 0; j < 4; j++) s[nt][j] *= scale;
        }

        float mx0 = -INFINITY, mx1 = -INFINITY;
#pragma unroll
        for (int nt = 0; nt < 8; nt++) {
            mx0 = fmaxf(mx0, fmaxf(s[nt][0], s[nt][1]));
            mx1 = fmaxf(mx1, fmaxf(s[nt][2], s[nt][3]));
        }
        mx0 = fmaxf(mx0, __shfl_xor_sync(0xffffffffu, mx0, 1));
        mx0 = fmaxf(mx0, __shfl_xor_sync(0xffffffffu, mx0, 2));
        mx1 = fmaxf(mx1, __shfl_xor_sync(0xffffffffu, mx1, 1));
        mx1 = fmaxf(mx1, __shfl_xor_sync(0xffffffffu, mx1, 2));

        float mn0 = fmaxf(m0, mx0), mn1 = fmaxf(m1, mx1);
        float a0 = __expf(m0 - mn0), a1 = __expf(m1 - mn1);
        m0 = mn0; m1 = mn1;

        float rs0 = 0.f, rs1 = 0.f;
#pragma unroll
        for (int nt = 0; nt < 8; nt++) {
            s[nt][0] = __expf(s[nt][0] - mn0);
            s[nt][1] = __expf(s[nt][1] - mn0);
            s[nt][2] = __expf(s[nt][2] - mn1);
            s[nt][3] = __expf(s[nt][3] - mn1);
            rs0 += s[nt][0] + s[nt][1];
            rs1 += s[nt][2] + s[nt][3];
        }
        rs0 += __shfl_xor_sync(0xffffffffu, rs0, 1);
        rs0 += __shfl_xor_sync(0xffffffffu, rs0, 2);
        rs1 += __shfl_xor_sync(0xffffffffu, rs1, 1);
        rs1 += __shfl_xor_sync(0xffffffffu, rs1, 2);
        l0 = l0 * a0 + rs0;
        l1 = l1 * a1 + rs1;

#pragma unroll
        for (int nt = 0; nt < 8; nt++) {
            o[nt][0] *= a0; o[nt][1] *= a0;
            o[nt][2] *= a1; o[nt][3] *= a1;
        }

        {
            char* p0 = Ps + lrow0 * HROWB;
            char* p1 = Ps + lrow1 * HROWB;
#pragma unroll
            for (int nt = 0; nt < 8; nt++) {
                int off = nt * 16 + 4 * lk;
                *(__half2*)(p0 + off) = __floats2half2_rn(s[nt][0], s[nt][1]);
                *(__half2*)(p1 + off) = __floats2half2_rn(s[nt][2], s[nt][3]);
            }
        }
        __syncwarp();

        uint32_t pf[4][4];
        {
            const char* p0 = Ps + lrow0 * HROWB;
            const char* p1 = Ps + lrow1 * HROWB;
#pragma unroll
            for (int kt = 0; kt < 4; kt++) {
                pf[kt][0] = *(const uint32_t*)(p0 + 4 * lk + 32 * kt);
                pf[kt][1] = *(const uint32_t*)(p1 + 4 * lk + 32 * kt);
                pf[kt][2] = *(const uint32_t*)(p0 + 4 * lk + 32 * kt + 16);
                pf[kt][3] = *(const uint32_t*)(p1 + 4 * lk + 32 * kt + 16);
            }
        }

#pragma unroll
        for (int nt = 0; nt < 8; nt++) {
#pragma unroll
            for (int g = 0; g < 2; g++) {
                uint32_t vb[4];
                ldsm_x4_t(vb, vs_b + (uint32_t)(32 * g + lane) * HROWB + nt * 16);
                mma16n8k16(o[nt], pf[2 * g], vb);
                mma16n8k16(o[nt], pf[2 * g + 1], vb + 2);
            }
        }
        __syncthreads();
    }

    const int b = bh >> 4, h = bh & 15;
    const float inv0 = 1.0f / l0, inv1 = 1.0f / l1;
    const int t0 = qb * 64 + lrow0, t1 = qb * 64 + lrow1;
    __half* dst0 = Yg + ((size_t)(b * Tt + t0)) * Cc + h * 64;
    __half* dst1 = Yg + ((size_t)(b * Tt + t1)) * Cc + h * 64;
#pragma unroll
    for (int nt = 0; nt < 8; nt++) {
        int d = nt * 8 + lk * 2;
        *(__half2*)(dst0 + d) = __floats2half2_rn(o[nt][0] * inv0, o[nt][1] * inv0);
        *(__half2*)(dst1 + d) = __floats2half2_rn(o[nt][2] * inv1, o[nt][3] * inv1);
    }
}

// ---------------------------------------------------------------------------
extern "C" void kernel_launch(void* const* d_in, const int* in_sizes, int n_in,
                              void* d_out, int out_size)
{
    const float* xq = (const float*)d_in[0];
    const float* xk = (const float*)d_in[1];
    const float* xv = (const float*)d_in[2];
    const float* Wq = (const float*)d_in[3];
    const float* Wk = (const float*)d_in[4];
    const float* Wv = (const float*)d_in[5];
    const float* Wo = (const float*)d_in[6];
    const float* bo = (const float*)d_in[7];
    float* out = (float*)d_out;

    __half *hxq, *hxk, *hxv, *hWq, *hWk, *hWv, *hWo, *Qp, *Kp, *Vp, *Yp;
    cudaGetSymbolAddress((void**)&hxq, g_hxq);
    cudaGetSymbolAddress((void**)&hxk, g_hxk);
    cudaGetSymbolAddress((void**)&hxv, g_hxv);
    cudaGetSymbolAddress((void**)&hWq, g_hWq);
    cudaGetSymbolAddress((void**)&hWk, g_hWk);
    cudaGetSymbolAddress((void**)&hWv, g_hWv);
    cudaGetSymbolAddress((void**)&hWo, g_hWo);
    cudaGetSymbolAddress((void**)&Qp, g_Q);
    cudaGetSymbolAddress((void**)&Kp, g_K);
    cudaGetSymbolAddress((void**)&Vp, g_V);
    cudaGetSymbolAddress((void**)&Yp, g_Y);

    cudaFuncSetAttribute(qkv_gemm, cudaFuncAttributeMaxDynamicSharedMemorySize, GEMM_SMEM);
    cudaFuncSetAttribute(oproj_gemm, cudaFuncAttributeMaxDynamicSharedMemorySize, GEMM_SMEM);
    cudaFuncSetAttribute(flash_mma, cudaFuncAttributeMaxDynamicSharedMemorySize, FA_SMEM);

    CvtArgs ca;
    const int NX4 = Mrows * Cc / 4;
    const int NW4 = Cc * Cc / 4;
    ca.src[0] = (const float4*)xq; ca.dst[0] = (uint2*)hxq; ca.n4[0] = NX4;
    ca.src[1] = (const float4*)xk; ca.dst[1] = (uint2*)hxk; ca.n4[1] = NX4;
    ca.src[2] = (const float4*)xv; ca.dst[2] = (uint2*)hxv; ca.n4[2] = NX4;
    ca.src[3] = (const float4*)Wq; ca.dst[3] = (uint2*)hWq; ca.n4[3] = NW4;
    ca.src[4] = (const float4*)Wk; ca.dst[4] = (uint2*)hWk; ca.n4[4] = NW4;
    ca.src[5] = (const float4*)Wv; ca.dst[5] = (uint2*)hWv; ca.n4[5] = NW4;
    ca.src[6] = (const float4*)Wo; ca.dst[6] = (uint2*)hWo; ca.n4[6] = NW4;
    cvt_kernel<<<dim3(1024, 7), 256>>>(ca);

    QKVArgs qa;
    qa.A[0] = hxq; qa.W[0] = hWq; qa.out[0] = Qp;
    qa.A[1] = hxk; qa.W[1] = hWk; qa.out[1] = Kp;
    qa.A[2] = hxv; qa.W[2] = hWv; qa.out[2] = Vp;
    qkv_gemm<<<dim3(Cc / 128, Mrows / 128, 3), 256, GEMM_SMEM>>>(qa);

    flash_mma<<<dim3(Tt / 64, Bb * Hh), 128, FA_SMEM>>>(Qp, Kp, Vp, Yp);

    oproj_gemm<<<dim3(Cc / 128, Mrows / 128), 256, GEMM_SMEM>>>(Yp, hWo, bo, out);
}

// round 9
// speedup vs baseline: 7.2265x; 1.0333x over previous
#include <cuda_runtime.h>
#include <cuda_fp16.h>
#include <math.h>
#include <stdint.h>

// Problem constants
#define Bb 4
#define Tt 2048
#define Cc 1024
#define Hh 16
#define HD 64
#define Mrows (Bb*Tt)   // 8192
#define GK 1024

// ---------------------------------------------------------------------------
// Helpers
// ---------------------------------------------------------------------------
__device__ __forceinline__ uint32_t smem_u32(const void* p) {
    uint32_t a;
    asm("{ .reg .u64 t; cvta.to.shared.u64 t, %1; cvt.u32.u64 %0, t; }"
        : "=r"(a) : "l"(p));
    return a;
}

__device__ __forceinline__ void cp_async16(uint32_t dst, const void* src) {
    asm volatile("cp.async.cg.shared.global [%0], [%1], 16;"
                 :: "r"(dst), "l"(src) : "memory");
}
#define CP_COMMIT() asm volatile("cp.async.commit_group;" ::: "memory")
#define CP_WAIT0()  asm volatile("cp.async.wait_group 0;" ::: "memory")
#define CP_WAIT1()  asm volatile("cp.async.wait_group 1;" ::: "memory")

// mma.sync m16n8k16 fp16 inputs, fp32 accumulate
__device__ __forceinline__ void mma16n8k16(
    float* c, const uint32_t* a, const uint32_t* b)
{
    asm volatile(
        "mma.sync.aligned.m16n8k16.row.col.f32.f16.f16.f32 "
        "{%0,%1,%2,%3}, {%4,%5,%6,%7}, {%8,%9}, {%0,%1,%2,%3};"
        : "+f"(c[0]), "+f"(c[1]), "+f"(c[2]), "+f"(c[3])
        : "r"(a[0]), "r"(a[1]), "r"(a[2]), "r"(a[3]),
          "r"(b[0]), "r"(b[1]));
}

__device__ __forceinline__ void ldsm_x4(uint32_t* r, uint32_t addr) {
    asm volatile(
        "ldmatrix.sync.aligned.m8n8.x4.shared.b16 {%0,%1,%2,%3}, [%4];"
        : "=r"(r[0]), "=r"(r[1]), "=r"(r[2]), "=r"(r[3]) : "r"(addr));
}
__device__ __forceinline__ void ldsm_x4_t(uint32_t* r, uint32_t addr) {
    asm volatile(
        "ldmatrix.sync.aligned.m8n8.x4.trans.shared.b16 {%0,%1,%2,%3}, [%4];"
        : "=r"(r[0]), "=r"(r[1]), "=r"(r[2]), "=r"(r[3]) : "r"(addr));
}

__device__ __forceinline__ uint32_t pack_h2(float a, float b) {
    __half2 h = __floats2half2_rn(a, b);
    return *reinterpret_cast<uint32_t*>(&h);
}

// ---------------------------------------------------------------------------
// Scratch (allocation-free: __device__ globals)
// ---------------------------------------------------------------------------
__device__ __half g_hxq[(size_t)Mrows*Cc];
__device__ __half g_hxk[(size_t)Mrows*Cc];
__device__ __half g_hxv[(size_t)Mrows*Cc];
__device__ __half g_hWq[(size_t)Cc*Cc];
__device__ __half g_hWk[(size_t)Cc*Cc];
__device__ __half g_hWv[(size_t)Cc*Cc];
__device__ __half g_hWo[(size_t)Cc*Cc];
__device__ __half g_Q[(size_t)Bb*Hh*Tt*HD];
__device__ __half g_K[(size_t)Bb*Hh*Tt*HD];
__device__ __half g_V[(size_t)Bb*Hh*Tt*HD];
__device__ __half g_Y[(size_t)Bb*Tt*Cc];

// ---------------------------------------------------------------------------
// Batched fp32 -> fp16 convert
// ---------------------------------------------------------------------------
struct CvtArgs {
    const float4* src[7];
    uint2*        dst[7];
    int           n4[7];
};

__global__ __launch_bounds__(256) void cvt_kernel(CvtArgs a) {
    int j = blockIdx.y;
    const float4* __restrict__ s = a.src[j];
    uint2* __restrict__ d = a.dst[j];
    int n4 = a.n4[j];
    int stride = gridDim.x * blockDim.x;
    for (int i = blockIdx.x * blockDim.x + threadIdx.x; i < n4; i += stride) {
        float4 v = s[i];
        uint2 o;
        o.x = pack_h2(v.x, v.y);
        o.y = pack_h2(v.z, v.w);
        d[i] = o;
    }
}

// ---------------------------------------------------------------------------
// GEMM core: BM=128, BN=128, BK=64, 8 warps (2m x 4n), warp tile 64x32.
// Single __syncthreads per K-iteration; loads overlap MMA.
// ---------------------------------------------------------------------------
#define HROWB 144               // bytes per smem row (72 halves)
#define GTILE (128*HROWB)       // 18432 B
#define GSTAGE (2*GTILE)        // 36864 B
#define GEMM_SMEM (2*GSTAGE)    // 73728 B
#define GKT (GK/64)             // 16

__device__ __forceinline__ void gemm_core(
    const __half* __restrict__ A, const __half* __restrict__ W,
    int bm, int bn, uint32_t sbase,
    int tid, int wm, int wn, int lane, float c[4][4][4])
{
#pragma unroll
    for (int i = 0; i < 4; i++)
#pragma unroll
        for (int j = 0; j < 4; j++)
#pragma unroll
            for (int r = 0; r < 4; r++) c[i][j][r] = 0.f;

    const int ch = tid & 7;
    const int rb = tid >> 3;
    const uint32_t lmrow = (uint32_t)(lane & 15) * HROWB + ((lane >> 4) << 4);

    auto issue_stage = [&](int stage, int k0) {
        uint32_t a_s = sbase + stage * GSTAGE;
        uint32_t b_s = a_s + GTILE;
#pragma unroll
        for (int i = 0; i < 4; i++) {
            int r = rb + i * 32;
            uint32_t so = (uint32_t)r * HROWB + ch * 16;
            cp_async16(a_s + so, A + (size_t)(bm + r) * GK + k0 + ch * 8);
            cp_async16(b_s + so, W + (size_t)(bn + r) * GK + k0 + ch * 8);
        }
        CP_COMMIT();
    };

    issue_stage(0, 0);

    for (int it = 0; it < GKT; ++it) {
        CP_WAIT0();            // stage it resident
        __syncthreads();       // all warps done with stage it-1 buffer
        if (it + 1 < GKT)
            issue_stage((it + 1) & 1, (it + 1) * 64);   // overlaps MMA below

        uint32_t as_b = sbase + (it & 1) * GSTAGE;
        uint32_t bs_b = as_b + GTILE;

#pragma unroll
        for (int ks = 0; ks < 4; ks++) {
            uint32_t af[4][4], bf[2][4];
#pragma unroll
            for (int mt = 0; mt < 4; mt++)
                ldsm_x4(af[mt],
                        as_b + (uint32_t)(wm * 64 + mt * 16) * HROWB + lmrow + ks * 32);
#pragma unroll
            for (int pr = 0; pr < 2; pr++)
                ldsm_x4(bf[pr],
                        bs_b + (uint32_t)(wn * 32 + pr * 16) * HROWB + lmrow + ks * 32);
#pragma unroll
            for (int mt = 0; mt < 4; mt++)
#pragma unroll
                for (int nt = 0; nt < 4; nt++) {
                    uint32_t b2[2];
                    b2[0] = bf[nt >> 1][nt & 1];
                    b2[1] = bf[nt >> 1][(nt & 1) + 2];
                    mma16n8k16(c[mt][nt], af[mt], b2);
                }
        }
    }
}

// Merged Q/K/V projection
struct QKVArgs {
    const __half* A[3];
    const __half* W[3];
    __half*       out[3];
};

__global__ __launch_bounds__(256, 2) void qkv_gemm(QKVArgs args)
{
    extern __shared__ __align__(16) char dsm[];
    const int tid = threadIdx.x;
    const int wid = tid >> 5, lane = tid & 31;
    const int wm = wid & 1, wn = wid >> 1;
    const int bm = blockIdx.y * 128, bn = blockIdx.x * 128;
    const int g = blockIdx.z;
    const int lg = lane >> 2, lk = lane & 3;

    float c[4][4][4];
    gemm_core(args.A[g], args.W[g], bm, bn, smem_u32(dsm),
              tid, wm, wn, lane, c);

    __half* out = args.out[g];
#pragma unroll
    for (int mt = 0; mt < 4; mt++) {
        int r0 = bm + wm * 64 + mt * 16 + lg;
#pragma unroll
        for (int nt = 0; nt < 4; nt++) {
            int n = bn + wn * 32 + nt * 8 + lk * 2;
            int h = n >> 6, d = n & 63;
            int b0 = r0 >> 11, t0 = r0 & (Tt - 1);
            *(__half2*)(out + ((size_t)(b0 * Hh + h) * Tt + t0) * HD + d) =
                __floats2half2_rn(c[mt][nt][0], c[mt][nt][1]);
            int r1 = r0 + 8;
            int b1 = r1 >> 11, t1 = r1 & (Tt - 1);
            *(__half2*)(out + ((size_t)(b1 * Hh + h) * Tt + t1) * HD + d) =
                __floats2half2_rn(c[mt][nt][2], c[mt][nt][3]);
        }
    }
}

// O-projection: fp32 out + bias
__global__ __launch_bounds__(256, 2) void oproj_gemm(
    const __half* __restrict__ A, const __half* __restrict__ W,
    const float* __restrict__ bias, float* __restrict__ out)
{
    extern __shared__ __align__(16) char dsm[];
    const int tid = threadIdx.x;
    const int wid = tid >> 5, lane = tid & 31;
    const int wm = wid & 1, wn = wid >> 1;
    const int bm = blockIdx.y * 128, bn = blockIdx.x * 128;
    const int lg = lane >> 2, lk = lane & 3;

    float c[4][4][4];
    gemm_core(A, W, bm, bn, smem_u32(dsm), tid, wm, wn, lane, c);

#pragma unroll
    for (int mt = 0; mt < 4; mt++) {
        int r0 = bm + wm * 64 + mt * 16 + lg;
#pragma unroll
        for (int nt = 0; nt < 4; nt++) {
            int n = bn + wn * 32 + nt * 8 + lk * 2;
            float2 bv = *(const float2*)(bias + n);
            *(float2*)(out + (size_t)r0 * Cc + n) =
                make_float2(c[mt][nt][0] + bv.x, c[mt][nt][1] + bv.y);
            *(float2*)(out + (size_t)(r0 + 8) * Cc + n) =
                make_float2(c[mt][nt][2] + bv.x, c[mt][nt][3] + bv.y);
        }
    }
}

// ---------------------------------------------------------------------------
// fp16 tensor-core causal flash attention.
// Single sync per K-tile; K via ldmatrix; P passed in registers (no smem).
// ---------------------------------------------------------------------------
#define FT_BYTES (64*HROWB)       // 9216 B
#define FA_SMEM (5*FT_BYTES)      // 46080 B (Q staged in 5th tile)

__global__ __launch_bounds__(128) void flash_mma(
    const __half* __restrict__ Qg, const __half* __restrict__ Kg,
    const __half* __restrict__ Vg, __half* __restrict__ Yg)
{
    extern __shared__ __align__(16) char fsm[];
    const uint32_t sb = smem_u32(fsm);
    const uint32_t ps_b = sb + 4 * FT_BYTES;

    const int tid = threadIdx.x;
    const int w = tid >> 5, lane = tid & 31;
    const int lg = lane >> 2, lk = lane & 3;
    const int qb = blockIdx.x;
    const int bh = blockIdx.y;

    const __half* Qbase = Qg + ((size_t)bh * Tt + qb * 64) * HD;
    const __half* Kbase = Kg + (size_t)bh * Tt * HD;
    const __half* Vbase = Vg + (size_t)bh * Tt * HD;

    const int lrow0 = w * 16 + lg;
    const int lrow1 = lrow0 + 8;
    const uint32_t lmrow = (uint32_t)(lane & 15) * HROWB + ((lane >> 4) << 4);

    const int ch = tid & 7;
    const int rb = tid >> 3;

    // ---- stage Q (group), then tile 0 (group) ----
#pragma unroll
    for (int i = 0; i < 4; i++) {
        int r = rb + i * 16;
        cp_async16(ps_b + (uint32_t)r * HROWB + ch * 16,
                   Qbase + (size_t)r * HD + ch * 8);
    }
    CP_COMMIT();

    auto issue_tile = [&](int kb) {
        uint32_t k_s = sb + (kb & 1) * 2 * FT_BYTES;
        uint32_t v_s = k_s + FT_BYTES;
#pragma unroll
        for (int i = 0; i < 4; i++) {
            int r = rb + i * 16;
            uint32_t so = (uint32_t)r * HROWB + ch * 16;
            size_t g = (size_t)(kb * 64 + r) * HD + ch * 8;
            cp_async16(k_s + so, Kbase + g);
            cp_async16(v_s + so, Vbase + g);
        }
        CP_COMMIT();
    };

    issue_tile(0);

    CP_WAIT1();        // Q resident (tile0 may still be in flight)
    __syncthreads();
    uint32_t qf[4][4];
    {
        const char* p0 = (const char*)fsm + 4 * FT_BYTES + lrow0 * HROWB;
        const char* p1 = (const char*)fsm + 4 * FT_BYTES + lrow1 * HROWB;
#pragma unroll
        for (int kt = 0; kt < 4; kt++) {
            qf[kt][0] = *(const uint32_t*)(p0 + 4 * lk + 32 * kt);
            qf[kt][1] = *(const uint32_t*)(p1 + 4 * lk + 32 * kt);
            qf[kt][2] = *(const uint32_t*)(p0 + 4 * lk + 32 * kt + 16);
            qf[kt][3] = *(const uint32_t*)(p1 + 4 * lk + 32 * kt + 16);
        }
    }

    float o[8][4];
#pragma unroll
    for (int nt = 0; nt < 8; nt++)
#pragma unroll
        for (int j = 0; j < 4; j++) o[nt][j] = 0.f;
    float m0 = -INFINITY, m1 = -INFINITY, l0 = 0.f, l1 = 0.f;
    const float scale = 0.125f;

    for (int kb = 0; kb <= qb; kb++) {
        CP_WAIT0();            // tile kb resident
        __syncthreads();       // all warps done with buffer being refilled
        if (kb + 1 <= qb)
            issue_tile(kb + 1);    // overlaps compute below

        const uint32_t ks_b = sb + (kb & 1) * 2 * FT_BYTES;
        const uint32_t vs_b = ks_b + FT_BYTES;

        // ---- S = Q @ K^T (K fragments via ldmatrix) ----
        float s[8][4];
#pragma unroll
        for (int nt = 0; nt < 8; nt++)
#pragma unroll
            for (int j = 0; j < 4; j++) s[nt][j] = 0.f;
#pragma unroll
        for (int pr = 0; pr < 4; pr++) {
            uint32_t base = ks_b + (uint32_t)(pr * 16) * HROWB + lmrow;
#pragma unroll
            for (int kt = 0; kt < 4; kt++) {
                uint32_t kf[4];
                ldsm_x4(kf, base + kt * 32);
                uint32_t b0[2] = {kf[0], kf[2]};
                uint32_t b1[2] = {kf[1], kf[3]};
                mma16n8k16(s[2 * pr], qf[kt], b0);
                mma16n8k16(s[2 * pr + 1], qf[kt], b1);
            }
        }

        // ---- scale + causal mask (diagonal tile only) ----
        if (kb == qb) {
#pragma unroll
            for (int nt = 0; nt < 8; nt++) {
                int c0 = nt * 8 + lk * 2, c1 = c0 + 1;
                s[nt][0] = (c0 > lrow0) ? -INFINITY : s[nt][0] * scale;
                s[nt][1] = (c1 > lrow0) ? -INFINITY : s[nt][1] * scale;
                s[nt][2] = (c0 > lrow1) ? -INFINITY : s[nt][2] * scale;
                s[nt][3] = (c1 > lrow1) ? -INFINITY : s[nt][3] * scale;
            }
        } else {
#pragma unroll
            for (int nt = 0; nt < 8; nt++)
#pragma unroll
                for (int j = 0; j < 4; j++) s[nt][j] *= scale;
        }

        // ---- online softmax ----
        float mx0 = -INFINITY, mx1 = -INFINITY;
#pragma unroll
        for (int nt = 0; nt < 8; nt++) {
            mx0 = fmaxf(mx0, fmaxf(s[nt][0], s[nt][1]));
            mx1 = fmaxf(mx1, fmaxf(s[nt][2], s[nt][3]));
        }
        mx0 = fmaxf(mx0, __shfl_xor_sync(0xffffffffu, mx0, 1));
        mx0 = fmaxf(mx0, __shfl_xor_sync(0xffffffffu, mx0, 2));
        mx1 = fmaxf(mx1, __shfl_xor_sync(0xffffffffu, mx1, 1));
        mx1 = fmaxf(mx1, __shfl_xor_sync(0xffffffffu, mx1, 2));

        float mn0 = fmaxf(m0, mx0), mn1 = fmaxf(m1, mx1);
        float a0 = __expf(m0 - mn0), a1 = __expf(m1 - mn1);
        m0 = mn0; m1 = mn1;

        float rs0 = 0.f, rs1 = 0.f;
#pragma unroll
        for (int nt = 0; nt < 8; nt++) {
            s[nt][0] = __expf(s[nt][0] - mn0);
            s[nt][1] = __expf(s[nt][1] - mn0);
            s[nt][2] = __expf(s[nt][2] - mn1);
            s[nt][3] = __expf(s[nt][3] - mn1);
            rs0 += s[nt][0] + s[nt][1];
            rs1 += s[nt][2] + s[nt][3];
        }
        rs0 += __shfl_xor_sync(0xffffffffu, rs0, 1);
        rs0 += __shfl_xor_sync(0xffffffffu, rs0, 2);
        rs1 += __shfl_xor_sync(0xffffffffu, rs1, 1);
        rs1 += __shfl_xor_sync(0xffffffffu, rs1, 2);
        l0 = l0 * a0 + rs0;
        l1 = l1 * a1 + rs1;

#pragma unroll
        for (int nt = 0; nt < 8; nt++) {
            o[nt][0] *= a0; o[nt][1] *= a0;
            o[nt][2] *= a1; o[nt][3] *= a1;
        }

        // ---- P fragments directly from S registers (C-layout == A-layout) ----
        uint32_t pf[4][4];
#pragma unroll
        for (int kt = 0; kt < 4; kt++) {
            pf[kt][0] = pack_h2(s[2 * kt][0],     s[2 * kt][1]);
            pf[kt][1] = pack_h2(s[2 * kt][2],     s[2 * kt][3]);
            pf[kt][2] = pack_h2(s[2 * kt + 1][0], s[2 * kt + 1][1]);
            pf[kt][3] = pack_h2(s[2 * kt + 1][2], s[2 * kt + 1][3]);
        }

        // ---- O += P @ V ----
#pragma unroll
        for (int nt = 0; nt < 8; nt++) {
#pragma unroll
            for (int g = 0; g < 2; g++) {
                uint32_t vb[4];
                ldsm_x4_t(vb, vs_b + (uint32_t)(32 * g + lane) * HROWB + nt * 16);
                mma16n8k16(o[nt], pf[2 * g], vb);
                mma16n8k16(o[nt], pf[2 * g + 1], vb + 2);
            }
        }
    }

    // ---- epilogue ----
    const int b = bh >> 4, h = bh & 15;
    const float inv0 = 1.0f / l0, inv1 = 1.0f / l1;
    const int t0 = qb * 64 + lrow0, t1 = qb * 64 + lrow1;
    __half* dst0 = Yg + ((size_t)(b * Tt + t0)) * Cc + h * 64;
    __half* dst1 = Yg + ((size_t)(b * Tt + t1)) * Cc + h * 64;
#pragma unroll
    for (int nt = 0; nt < 8; nt++) {
        int d = nt * 8 + lk * 2;
        *(__half2*)(dst0 + d) = __floats2half2_rn(o[nt][0] * inv0, o[nt][1] * inv0);
        *(__half2*)(dst1 + d) = __floats2half2_rn(o[nt][2] * inv1, o[nt][3] * inv1);
    }
}

// ---------------------------------------------------------------------------
extern "C" void kernel_launch(void* const* d_in, const int* in_sizes, int n_in,
                              void* d_out, int out_size)
{
    const float* xq = (const float*)d_in[0];
    const float* xk = (const float*)d_in[1];
    const float* xv = (const float*)d_in[2];
    const float* Wq = (const float*)d_in[3];
    const float* Wk = (const float*)d_in[4];
    const float* Wv = (const float*)d_in[5];
    const float* Wo = (const float*)d_in[6];
    const float* bo = (const float*)d_in[7];
    float* out = (float*)d_out;

    __half *hxq, *hxk, *hxv, *hWq, *hWk, *hWv, *hWo, *Qp, *Kp, *Vp, *Yp;
    cudaGetSymbolAddress((void**)&hxq, g_hxq);
    cudaGetSymbolAddress((void**)&hxk, g_hxk);
    cudaGetSymbolAddress((void**)&hxv, g_hxv);
    cudaGetSymbolAddress((void**)&hWq, g_hWq);
    cudaGetSymbolAddress((void**)&hWk, g_hWk);
    cudaGetSymbolAddress((void**)&hWv, g_hWv);
    cudaGetSymbolAddress((void**)&hWo, g_hWo);
    cudaGetSymbolAddress((void**)&Qp, g_Q);
    cudaGetSymbolAddress((void**)&Kp, g_K);
    cudaGetSymbolAddress((void**)&Vp, g_V);
    cudaGetSymbolAddress((void**)&Yp, g_Y);

    cudaFuncSetAttribute(qkv_gemm, cudaFuncAttributeMaxDynamicSharedMemorySize, GEMM_SMEM);
    cudaFuncSetAttribute(oproj_gemm, cudaFuncAttributeMaxDynamicSharedMemorySize, GEMM_SMEM);
    cudaFuncSetAttribute(flash_mma, cudaFuncAttributeMaxDynamicSharedMemorySize, FA_SMEM);

    CvtArgs ca;
    const int NX4 = Mrows * Cc / 4;
    const int NW4 = Cc * Cc / 4;
    ca.src[0] = (const float4*)xq; ca.dst[0] = (uint2*)hxq; ca.n4[0] = NX4;
    ca.src[1] = (const float4*)xk; ca.dst[1] = (uint2*)hxk; ca.n4[1] = NX4;
    ca.src[2] = (const float4*)xv; ca.dst[2] = (uint2*)hxv; ca.n4[2] = NX4;
    ca.src[3] = (const float4*)Wq; ca.dst[3] = (uint2*)hWq; ca.n4[3] = NW4;
    ca.src[4] = (const float4*)Wk; ca.dst[4] = (uint2*)hWk; ca.n4[4] = NW4;
    ca.src[5] = (const float4*)Wv; ca.dst[5] = (uint2*)hWv; ca.n4[5] = NW4;
    ca.src[6] = (const float4*)Wo; ca.dst[6] = (uint2*)hWo; ca.n4[6] = NW4;
    cvt_kernel<<<dim3(1024, 7), 256>>>(ca);

    QKVArgs qa;
    qa.A[0] = hxq; qa.W[0] = hWq; qa.out[0] = Qp;
    qa.A[1] = hxk; qa.W[1] = hWk; qa.out[1] = Kp;
    qa.A[2] = hxv; qa.W[2] = hWv; qa.out[2] = Vp;
    qkv_gemm<<<dim3(Cc / 128, Mrows / 128, 3), 256, GEMM_SMEM>>>(qa);

    flash_mma<<<dim3(Tt / 64, Bb * Hh), 128, FA_SMEM>>>(Qp, Kp, Vp, Yp);

    oproj_gemm<<<dim3(Cc / 128, Mrows / 128), 256, GEMM_SMEM>>>(Yp, hWo, bo, out);
}